// round 1
// baseline (speedup 1.0000x reference)
#include <cuda_runtime.h>
#include <cuda_bf16.h>
#include <cstdint>

#define BB 256
#define TT 336
#define DD 128
#define HH 1024
#define K1 1152
#define K2 2048
#define FOURH 4096

// ---------------- device-global scratch (no allocs allowed) ----------------
__device__ __nv_bfloat16 g_W1[K1 * FOURH];        // bf16 copy of W1
__device__ __nv_bfloat16 g_W2[K2 * FOURH];        // bf16 copy of W2
__device__ __nv_bfloat16 g_X[TT * BB * DD];       // features rearranged [t][b][d], bf16
__device__ __nv_bfloat16 g_h1[2][BB * HH];        // ping-pong hidden states (bf16)
__device__ __nv_bfloat16 g_h2[2][BB * HH];
__device__ float g_c1[BB * HH];
__device__ float g_c2[BB * HH];
__device__ float g_partial[BB];

// ---------------- helpers ----------------
__device__ __forceinline__ uint32_t smem_u32(const void* p) {
    return (uint32_t)__cvta_generic_to_shared(p);
}

__device__ __forceinline__ float sigmoidf_(float x) {
    return 1.f / (1.f + __expf(-x));
}

// ---------------- conversion / init kernels ----------------
__global__ void conv_w_kernel(const float* __restrict__ src, int which, int n) {
    for (int i = blockIdx.x * blockDim.x + threadIdx.x; i < n; i += gridDim.x * blockDim.x) {
        __nv_bfloat16 v = __float2bfloat16(src[i]);
        if (which == 0) g_W1[i] = v;
        else            g_W2[i] = v;
    }
}

__global__ void conv_x_kernel(const float* __restrict__ f) {
    int n = BB * TT * DD;
    for (int i = blockIdx.x * blockDim.x + threadIdx.x; i < n; i += gridDim.x * blockDim.x) {
        int b = i / (TT * DD);
        int r = i % (TT * DD);
        int t = r / DD;
        int d = r % DD;
        g_X[(size_t)t * BB * DD + b * DD + d] = __float2bfloat16(f[i]);
    }
}

__global__ void init_state_kernel() {
    int n = BB * HH;
    __nv_bfloat16 z = __float2bfloat16(0.f);
    for (int i = blockIdx.x * blockDim.x + threadIdx.x; i < n; i += gridDim.x * blockDim.x) {
        g_c1[i] = 0.f;
        g_c2[i] = 0.f;
        g_h1[0][i] = z;
        g_h2[0][i] = z;
    }
}

// ---------------- fused GEMM + LSTM cell step kernel ----------------
// Block tile: 64 rows (batch) x 32 H-cols -> z tile 64 x 128 (4 gates x 32 cols).
// 8 warps: 4 (M) x 2 (N); warp tile 16 x 64 via mma.sync m16n8k16 bf16.
#define AS_STRIDE 40    // 32 + 8 pad (bf16)
#define BS_STRIDE 136   // 128 + 8 pad (bf16)
#define ZS_STRIDE 132   // 128 + 4 pad (float)

__global__ __launch_bounds__(256, 1)
void lstm_step_kernel(int layer, int t, int pin, const float* __restrict__ bias) {
    __shared__ __align__(16) unsigned char smem_raw[64 * ZS_STRIDE * 4]; // 33792 B
    __nv_bfloat16* As = (__nv_bfloat16*)smem_raw;                 // [2][64][AS_STRIDE] = 10240 B
    __nv_bfloat16* Bs = (__nv_bfloat16*)(smem_raw + 10240);       // [2][32][BS_STRIDE] = 17408 B
    float* zs = (float*)smem_raw;                                 // [64][ZS_STRIDE] (reused post-GEMM)

    int K, boundk, lda0;
    const __nv_bfloat16 *A0, *A1, *Wm;
    float* cst;
    __nv_bfloat16* hout;
    const int pout = pin ^ 1;

    if (layer == 0) {
        K = K1; boundk = DD; lda0 = DD;
        A0 = g_X + (size_t)t * BB * DD;   // x_t
        A1 = g_h1[pin];                    // h1_{t-1}
        Wm = g_W1; cst = g_c1; hout = g_h1[pout];
    } else {
        K = K2; boundk = HH; lda0 = HH;
        A0 = g_h1[pout];                   // h1_t (just written by layer 0)
        A1 = g_h2[pin];                    // h2_{t-1}
        Wm = g_W2; cst = g_c2; hout = g_h2[pout];
    }

    const int n0 = blockIdx.x * 32;   // H-column base
    const int m0 = blockIdx.y * 64;   // batch-row base
    const int tid = threadIdx.x;
    const int lane = tid & 31;
    const int wid = tid >> 5;
    const int wm = wid & 3;           // warp M index (16 rows each)
    const int wn = wid >> 2;          // warp N index (64 z-cols each)

    // global-load thread mapping
    const int rowA = tid >> 2;        // 0..63
    const int quadA = tid & 3;        // 16B chunk within 32-col A tile

    float acc[8][4];
#pragma unroll
    for (int j = 0; j < 8; j++)
#pragma unroll
        for (int q = 0; q < 4; q++) acc[j][q] = 0.f;

    auto load_stage = [&](int kt, int s) {
        const int k0 = kt * 32;
        // A tile: 64 rows x 32 k (bf16), 16B per thread
        const __nv_bfloat16* gpA;
        if (k0 < boundk) gpA = A0 + (size_t)(m0 + rowA) * lda0 + k0 + quadA * 8;
        else             gpA = A1 + (size_t)(m0 + rowA) * HH + (k0 - boundk) + quadA * 8;
        uint32_t dstA = smem_u32(As + s * 64 * AS_STRIDE + rowA * AS_STRIDE + quadA * 8);
        asm volatile("cp.async.cg.shared.global [%0], [%1], 16;\n" :: "r"(dstA), "l"(gpA));
        // B tile: 32 k x 128 z-cols (4 gate chunks of 32), 2 x 16B per thread
#pragma unroll
        for (int i = 0; i < 2; i++) {
            int c = tid + i * 256;
            int kk = c >> 4;            // 0..31
            int nc = (c & 15) * 8;      // 0..120
            int g = nc >> 5;            // gate index
            int col = g * HH + n0 + (nc & 31);
            const __nv_bfloat16* gpB = Wm + (size_t)(k0 + kk) * FOURH + col;
            uint32_t dstB = smem_u32(Bs + s * 32 * BS_STRIDE + kk * BS_STRIDE + nc);
            asm volatile("cp.async.cg.shared.global [%0], [%1], 16;\n" :: "r"(dstB), "l"(gpB));
        }
    };

    load_stage(0, 0);
    asm volatile("cp.async.commit_group;\n" ::: "memory");

    const int nK = K >> 5;
    for (int kt = 0; kt < nK; ++kt) {
        const int s = kt & 1;
        if (kt + 1 < nK) load_stage(kt + 1, s ^ 1);
        asm volatile("cp.async.commit_group;\n" ::: "memory");
        asm volatile("cp.async.wait_group 1;\n" ::: "memory");
        __syncthreads();

#pragma unroll
        for (int ks = 0; ks < 2; ++ks) {
            // A fragments (16x16) via ldmatrix.x4
            uint32_t a0, a1, a2, a3;
            {
                int row = wm * 16 + (lane & 15);
                int colb = ks * 16 + (lane >> 4) * 8;
                uint32_t addr = smem_u32(As + s * 64 * AS_STRIDE + row * AS_STRIDE + colb);
                asm volatile("ldmatrix.sync.aligned.m8n8.x4.shared.b16 {%0,%1,%2,%3}, [%4];\n"
                             : "=r"(a0), "=r"(a1), "=r"(a2), "=r"(a3) : "r"(addr));
            }
#pragma unroll
            for (int j2 = 0; j2 < 4; j2++) {
                uint32_t b0, b1, b2, b3;
                int krow = ks * 16 + (lane & 7) + ((lane >> 3) & 1) * 8;
                int ncol = wn * 64 + j2 * 16 + (lane >> 4) * 8;
                uint32_t addr = smem_u32(Bs + s * 32 * BS_STRIDE + krow * BS_STRIDE + ncol);
                asm volatile("ldmatrix.sync.aligned.m8n8.x4.trans.shared.b16 {%0,%1,%2,%3}, [%4];\n"
                             : "=r"(b0), "=r"(b1), "=r"(b2), "=r"(b3) : "r"(addr));
                asm volatile("mma.sync.aligned.m16n8k16.row.col.f32.bf16.bf16.f32 "
                             "{%0,%1,%2,%3}, {%4,%5,%6,%7}, {%8,%9}, {%0,%1,%2,%3};\n"
                             : "+f"(acc[2 * j2][0]), "+f"(acc[2 * j2][1]),
                               "+f"(acc[2 * j2][2]), "+f"(acc[2 * j2][3])
                             : "r"(a0), "r"(a1), "r"(a2), "r"(a3), "r"(b0), "r"(b1));
                asm volatile("mma.sync.aligned.m16n8k16.row.col.f32.bf16.bf16.f32 "
                             "{%0,%1,%2,%3}, {%4,%5,%6,%7}, {%8,%9}, {%0,%1,%2,%3};\n"
                             : "+f"(acc[2 * j2 + 1][0]), "+f"(acc[2 * j2 + 1][1]),
                               "+f"(acc[2 * j2 + 1][2]), "+f"(acc[2 * j2 + 1][3])
                             : "r"(a0), "r"(a1), "r"(a2), "r"(a3), "r"(b2), "r"(b3));
            }
        }
        __syncthreads();
    }

    // ---- epilogue: stage z in smem, then fused LSTM cell ----
#pragma unroll
    for (int j = 0; j < 8; j++) {
        int col = wn * 64 + j * 8 + (lane & 3) * 2;
        int r = wm * 16 + (lane >> 2);
        zs[r * ZS_STRIDE + col]           = acc[j][0];
        zs[r * ZS_STRIDE + col + 1]       = acc[j][1];
        zs[(r + 8) * ZS_STRIDE + col]     = acc[j][2];
        zs[(r + 8) * ZS_STRIDE + col + 1] = acc[j][3];
    }
    __syncthreads();

#pragma unroll
    for (int e = tid; e < 64 * 32; e += 256) {
        int r = e >> 5;
        int hc = e & 31;
        float zi = zs[r * ZS_STRIDE + hc]        + bias[0 * HH + n0 + hc];
        float zj = zs[r * ZS_STRIDE + 32 + hc]   + bias[1 * HH + n0 + hc];
        float zf = zs[r * ZS_STRIDE + 64 + hc]   + bias[2 * HH + n0 + hc];
        float zo = zs[r * ZS_STRIDE + 96 + hc]   + bias[3 * HH + n0 + hc];
        int gi = (m0 + r) * HH + n0 + hc;
        float c = cst[gi];
        float nc = c * sigmoidf_(zf + 1.f) + sigmoidf_(zi) * tanhf(zj);
        float nh = tanhf(nc) * sigmoidf_(zo);
        cst[gi] = nc;
        hout[gi] = __float2bfloat16(nh);
    }
}

// ---------------- dense head + loss ----------------
__global__ void head_kernel(const float* __restrict__ Wd, const float* __restrict__ bd,
                            const float* __restrict__ labels) {
    const int b = blockIdx.x;
    const int lane = threadIdx.x & 31;
    const int w = threadIdx.x >> 5;
    const __nv_bfloat16* h = g_h2[0];  // final slot: T=336 even -> last write at parity 0
    __shared__ float warpsum[8];
    float total = 0.f;
    for (int l = w; l < 24; l += 8) {
        float s = 0.f;
        for (int k = lane; k < HH; k += 32)
            s += __bfloat162float(h[b * HH + k]) * Wd[k * 24 + l];
#pragma unroll
        for (int off = 16; off; off >>= 1) s += __shfl_xor_sync(0xffffffffu, s, off);
        if (lane == 0) {
            float pred = s + bd[l];
            float e = pred - labels[b * 24 + l];
            total += e * e;
        }
    }
    if (lane == 0) warpsum[w] = total;
    __syncthreads();
    if (threadIdx.x == 0) {
        float acc = 0.f;
#pragma unroll
        for (int i = 0; i < 8; i++) acc += warpsum[i];
        g_partial[b] = acc;
    }
}

__global__ void finish_kernel(float* __restrict__ out) {
    __shared__ float sh[256];
    sh[threadIdx.x] = g_partial[threadIdx.x];
    __syncthreads();
    for (int s = 128; s; s >>= 1) {
        if (threadIdx.x < s) sh[threadIdx.x] += sh[threadIdx.x + s];
        __syncthreads();
    }
    if (threadIdx.x == 0) out[0] = sh[0] / (float)(BB * 24);
}

// ---------------- launch ----------------
extern "C" void kernel_launch(void* const* d_in, const int* in_sizes, int n_in,
                              void* d_out, int out_size) {
    const float* features = (const float*)d_in[0];
    const float* labels   = (const float*)d_in[1];
    const float* W1       = (const float*)d_in[2];
    const float* b1       = (const float*)d_in[3];
    const float* W2       = (const float*)d_in[4];
    const float* b2       = (const float*)d_in[5];
    const float* Wd       = (const float*)d_in[6];
    const float* bd       = (const float*)d_in[7];
    float* out = (float*)d_out;

    conv_w_kernel<<<592, 256>>>(W1, 0, K1 * FOURH);
    conv_w_kernel<<<592, 256>>>(W2, 1, K2 * FOURH);
    conv_x_kernel<<<592, 256>>>(features);
    init_state_kernel<<<512, 256>>>();

    dim3 grid(32, 4);  // 32 H-col tiles x 4 batch tiles = 128 blocks
    for (int t = 0; t < TT; t++) {
        int p = t & 1;
        lstm_step_kernel<<<grid, 256>>>(0, t, p, b1);
        lstm_step_kernel<<<grid, 256>>>(1, t, p, b2);
    }

    head_kernel<<<BB, 256>>>(Wd, bd, labels);
    finish_kernel<<<1, 256>>>(out);
}

// round 3
// speedup vs baseline: 1.2215x; 1.2215x over previous
#include <cuda_runtime.h>
#include <cuda_bf16.h>
#include <cstdint>

#define BB 256
#define TT 336
#define DD 128
#define HH 1024
#define K1 1152
#define K2 2048
#define FOURH 4096

#define STAGES 5
#define PRE 3
#define STAGE_BYTES 32768         // A tile 16KB + B tile 16KB
#define SMEM_DYN (STAGES * STAGE_BYTES + 1024)

// ---- arch-feature gate: tcgen05 only exists on the 'a' / family-specific targets ----
#if defined(__CUDA_ARCH__) && \
    (defined(__CUDA_ARCH_FEAT_SM103_ALL) || defined(__CUDA_ARCH_FEAT_SM100_ALL) || \
     (defined(__CUDA_ARCH_SPECIFIC__) && (__CUDA_ARCH_SPECIFIC__ >= 1000)) || \
     (defined(__CUDA_ARCH_FAMILY_SPECIFIC__) && (__CUDA_ARCH_FAMILY_SPECIFIC__ >= 1000)))
#define HAS_TCGEN05 1
#else
#define HAS_TCGEN05 0
#endif

// ---------------- device-global scratch ----------------
// g_W1/g_W2 layout depends on dispatch path:
//   tcgen05 path: [nt*128 + gate*32 + c][K]  (K contiguous, transposed)
//   fallback path: [k][4096]                 (original, bf16)
__device__ __nv_bfloat16 g_W1[K1 * FOURH];
__device__ __nv_bfloat16 g_W2[K2 * FOURH];
__device__ __nv_bfloat16 g_X[TT * BB * DD];  // [t][b][d]
__device__ __nv_bfloat16 g_h1[2][BB * HH];
__device__ __nv_bfloat16 g_h2[2][BB * HH];
__device__ float g_c1[BB * HH];
__device__ float g_c2[BB * HH];
__device__ float g_partial[BB];

// ---------------- helpers ----------------
__device__ __forceinline__ uint32_t smem_u32(const void* p) {
    return (uint32_t)__cvta_generic_to_shared(p);
}
__device__ __forceinline__ float sigmoidf_(float x) { return 1.f / (1.f + __expf(-x)); }

// ---------------- conversion / init kernels ----------------
// tcgen05 path: transpose W[k][4096] (fp32) -> Wp[nt*128 + g*32 + c][K] (bf16)
__global__ void conv_w_t(const float* __restrict__ src, int which, int K) {
    __shared__ float tile[32][33];
    const int kb = blockIdx.x * 32, nt = blockIdx.y, g = blockIdx.z;
    const int tx = threadIdx.x, ty0 = threadIdx.y;
#pragma unroll
    for (int i = 0; i < 4; i++) {
        int ty = ty0 + i * 8;
        tile[ty][tx] = src[(size_t)(kb + ty) * FOURH + g * HH + nt * 32 + tx];
    }
    __syncthreads();
    __nv_bfloat16* dst = (which == 0) ? g_W1 : g_W2;
#pragma unroll
    for (int i = 0; i < 4; i++) {
        int ty = ty0 + i * 8;
        dst[(size_t)(nt * 128 + g * 32 + ty) * K + kb + tx] = __float2bfloat16(tile[tx][ty]);
    }
}

// fallback path: plain fp32 -> bf16 copy, original layout
__global__ void conv_w_kernel(const float* __restrict__ src, int which, int n) {
    for (int i = blockIdx.x * blockDim.x + threadIdx.x; i < n; i += gridDim.x * blockDim.x) {
        __nv_bfloat16 v = __float2bfloat16(src[i]);
        if (which == 0) g_W1[i] = v;
        else            g_W2[i] = v;
    }
}

__global__ void conv_x_kernel(const float* __restrict__ f) {
    int n = BB * TT * DD;
    for (int i = blockIdx.x * blockDim.x + threadIdx.x; i < n; i += gridDim.x * blockDim.x) {
        int b = i / (TT * DD);
        int r = i % (TT * DD);
        int t = r / DD;
        int d = r % DD;
        g_X[(size_t)t * BB * DD + b * DD + d] = __float2bfloat16(f[i]);
    }
}

__global__ void init_state_kernel() {
    int n = BB * HH;
    __nv_bfloat16 z = __float2bfloat16(0.f);
    for (int i = blockIdx.x * blockDim.x + threadIdx.x; i < n; i += gridDim.x * blockDim.x) {
        g_c1[i] = 0.f;
        g_c2[i] = 0.f;
        g_h1[0][i] = z;
        g_h2[0][i] = z;
    }
}

// ============================================================================
// tcgen05 PTX helpers (only compiled on 'a'-variant targets)
// ============================================================================
#if HAS_TCGEN05

__device__ __forceinline__ uint32_t elect_one_pred() {
    uint32_t pred;
    asm volatile(
        "{\n\t.reg .pred p;\n\t"
        "elect.sync _|p, 0xFFFFFFFF;\n\t"
        "selp.b32 %0, 1, 0, p;\n\t}"
        : "=r"(pred));
    return pred;
}

#define MBARRIER_INIT(mbar, count) \
    asm volatile("mbarrier.init.shared.b64 [%0], %1;" :: "r"((uint32_t)(mbar)), "r"((uint32_t)(count)) : "memory")

#define MBARRIER_WAIT_PARITY(mbar_addr, phase_parity) do {                          \
    uint32_t _mbar = (uint32_t)(mbar_addr);                                         \
    uint32_t _parity = (uint32_t)(phase_parity);                                    \
    uint32_t _done;                                                                 \
    asm volatile(                                                                   \
        "{\n\t.reg .pred p;\n\t"                                                    \
        "mbarrier.try_wait.parity.acquire.cta.shared::cta.b64 p, [%1], %2;\n\t"     \
        "selp.b32 %0, 1, 0, p;\n\t}"                                                \
        : "=r"(_done) : "r"(_mbar), "r"(_parity) : "memory");                       \
    if (!_done) {                                                                   \
        asm volatile(                                                               \
            "{\n\t.reg .pred P1;\n\t"                                               \
            "WAIT_LOOP_%=:\n\t"                                                     \
            "mbarrier.try_wait.parity.acquire.cta.shared::cta.b64 P1, [%0], %1, 0x989680;\n\t" \
            "@P1 bra.uni WAIT_DONE_%=;\n\t"                                         \
            "bra.uni WAIT_LOOP_%=;\n\t"                                             \
            "WAIT_DONE_%=:\n\t}"                                                    \
            :: "r"(_mbar), "r"(_parity) : "memory");                                \
    }                                                                               \
} while (0)

#define TCGEN05_ALLOC(smem_result_addr, nCols) \
    asm volatile("tcgen05.alloc.cta_group::1.sync.aligned.shared::cta.b32 [%0], %1;" \
                 :: "r"((uint32_t)(smem_result_addr)), "r"((uint32_t)(nCols)) : "memory")
#define TCGEN05_DEALLOC(tmem_addr, nCols) \
    asm volatile("tcgen05.dealloc.cta_group::1.sync.aligned.b32 %0, %1;" \
                 :: "r"(tmem_addr), "r"((uint32_t)(nCols)))
#define TCGEN05_RELINQUISH() \
    asm volatile("tcgen05.relinquish_alloc_permit.cta_group::1.sync.aligned;")
#define TCGEN05_COMMIT(mbar_addr) \
    asm volatile("tcgen05.commit.cta_group::1.mbarrier::arrive::one.shared::cluster.b64 [%0];" \
                 :: "r"((uint32_t)(mbar_addr)) : "memory")
#define TCGEN05_WAIT_LD()  asm volatile("tcgen05.wait::ld.sync.aligned;" ::: "memory")
#define TCGEN05_FENCE_AFTER()  asm volatile("tcgen05.fence::after_thread_sync;" ::: "memory")
#define TCGEN05_FENCE_BEFORE() asm volatile("tcgen05.fence::before_thread_sync;" ::: "memory")

#define TCGEN05_LD_X32(r, tmem_addr) \
    asm volatile( \
        "tcgen05.ld.sync.aligned.32x32b.x32.b32 " \
        "{%0, %1, %2, %3, %4, %5, %6, %7, " \
        " %8, %9, %10, %11, %12, %13, %14, %15, " \
        " %16, %17, %18, %19, %20, %21, %22, %23, " \
        " %24, %25, %26, %27, %28, %29, %30, %31}, [%32];" \
        : "=r"((r)[0]),  "=r"((r)[1]),  "=r"((r)[2]),  "=r"((r)[3]), \
          "=r"((r)[4]),  "=r"((r)[5]),  "=r"((r)[6]),  "=r"((r)[7]), \
          "=r"((r)[8]),  "=r"((r)[9]),  "=r"((r)[10]), "=r"((r)[11]), \
          "=r"((r)[12]), "=r"((r)[13]), "=r"((r)[14]), "=r"((r)[15]), \
          "=r"((r)[16]), "=r"((r)[17]), "=r"((r)[18]), "=r"((r)[19]), \
          "=r"((r)[20]), "=r"((r)[21]), "=r"((r)[22]), "=r"((r)[23]), \
          "=r"((r)[24]), "=r"((r)[25]), "=r"((r)[26]), "=r"((r)[27]), \
          "=r"((r)[28]), "=r"((r)[29]), "=r"((r)[30]), "=r"((r)[31]) \
        : "r"(tmem_addr))

__device__ __forceinline__ uint64_t sdesc_sw128(uint32_t addr) {
    return (2ULL << 61) | (1ULL << 46) | (64ULL << 32) | (1ULL << 16) |
           (uint64_t)((addr >> 4) & 0x3FFF);
}

// idesc kind::f16: dtype=F32, atype=btype=BF16, N=128, M=128, no transpose
#define MMA_IDESC ((1u << 4) | (1u << 7) | (1u << 10) | ((128u / 8) << 17) | ((128u / 16) << 24))

__device__ __forceinline__ void mma_f16_ss(uint32_t d, uint64_t ad, uint64_t bd,
                                           uint32_t idesc, unsigned en) {
    asm volatile(
        "{\n\t.reg .pred p;\n\t"
        "setp.ne.u32 p, %5, 0;\n\t"
        "tcgen05.mma.cta_group::1.kind::f16 [%0], %1, %2, %3, {%4, %4, %4, %4}, p;\n\t}"
        :: "r"(d), "l"(ad), "l"(bd), "r"(idesc), "r"(0u), "r"(en) : "memory");
}

#endif // HAS_TCGEN05

// ============================================================================
// tcgen05 fused GEMM + LSTM cell step kernel
// CTA tile: M=128 batch rows x N=128 z-cols (= 32 h-cols x 4 gates).
// Grid (32 ntiles, 2 mtiles). 256 threads: warp0 = MMA issuer, warps 1-7 = loaders.
// Compiled as an empty stub on non-'a' targets (never launched there — host
// dispatch checks numRegs of the loaded binary).
// ============================================================================
__global__ __launch_bounds__(256, 1)
void lstm_step_tc(int layer, int t, int pin, const float* __restrict__ bias) {
#if HAS_TCGEN05
    extern __shared__ __align__(1024) unsigned char sm[];
    const uint32_t smem_base = smem_u32(sm);
    const int tid = threadIdx.x;
    const int wid = tid >> 5;
    const int lane = tid & 31;
    const int nt = blockIdx.x;
    const int m0 = blockIdx.y * 128;

    const uint32_t ctrl = smem_base + STAGES * STAGE_BYTES;        // tmem ptr (16B)
    const uint32_t mbar0 = ctrl + 16;                              // ring mbars [STAGES]
    const uint32_t mbar_done = ctrl + 16 + 8 * STAGES;

    int K, nc, boundk, lda0;
    const __nv_bfloat16 *A0, *A1, *Wp;
    float* cst;
    __nv_bfloat16* hout;
    const int pout = pin ^ 1;
    if (layer == 0) {
        K = K1; nc = K1 / 64; boundk = DD; lda0 = DD;
        A0 = g_X + t * BB * DD; A1 = g_h1[pin];
        Wp = g_W1; cst = g_c1; hout = g_h1[pout];
    } else {
        K = K2; nc = K2 / 64; boundk = HH; lda0 = HH;
        A0 = g_h1[pout]; A1 = g_h2[pin];
        Wp = g_W2; cst = g_c2; hout = g_h2[pout];
    }

    if (wid == 0) TCGEN05_ALLOC(ctrl, 128);
    if (tid == 0) {
#pragma unroll
        for (int s = 0; s < STAGES; s++) MBARRIER_INIT(mbar0 + 8 * s, 1);
        MBARRIER_INIT(mbar_done, 1);
    }
    __syncthreads();
    uint32_t tmem_base;
    asm volatile("ld.shared.b32 %0, [%1];" : "=r"(tmem_base) : "r"(ctrl));

    // ---- loader ----
    auto load_chunk = [&](int j) {
        const int s = j % STAGES;
        const uint32_t sbase = smem_base + s * STAGE_BYTES;
        const int k0 = j * 64;
        const __nv_bfloat16* Abase;
        int lda;
        if (k0 < boundk) { Abase = A0 + k0; lda = lda0; }
        else             { Abase = A1 + (k0 - boundk); lda = HH; }
        for (int idx = tid - 32; idx < 2048; idx += 224) {
            const int half = idx >> 10;            // 0 = A, 1 = B
            const int r = (idx & 1023) >> 3;       // row 0..127
            const int ch = idx & 7;                // 16B chunk within 128B row
            const __nv_bfloat16* gp;
            if (half == 0) gp = Abase + (m0 + r) * lda + ch * 8;
            else           gp = Wp + (size_t)(nt * 128 + r) * K + k0 + ch * 8;
            uint32_t off = (r << 7) | (ch << 4);
            uint32_t sw = off ^ ((off >> 3) & 0x70);
            uint32_t dst = sbase + (half << 14) | 0;
            dst = sbase + (half << 14) + sw;
            asm volatile("cp.async.cg.shared.global [%0], [%1], 16;\n" :: "r"(dst), "l"(gp));
        }
    };

    if (wid > 0) {
#pragma unroll
        for (int j = 0; j < PRE; j++) {
            load_chunk(j);
            asm volatile("cp.async.commit_group;\n" ::: "memory");
        }
    }

    int ph[STAGES];
#pragma unroll
    for (int s = 0; s < STAGES; s++) ph[s] = 0;

    for (int c = 0; c < nc; ++c) {
        const int s = c % STAGES;
        if (wid > 0) {
            const int j = c + PRE;
            if (j < nc) {
                if (j >= STAGES) {
                    const int ss = j % STAGES;
                    MBARRIER_WAIT_PARITY(mbar0 + 8 * ss, ph[ss]);
                    ph[ss] ^= 1;
                }
                load_chunk(j);
            }
            asm volatile("cp.async.commit_group;\n" ::: "memory");
            asm volatile("cp.async.wait_group %0;\n" :: "n"(PRE) : "memory");
            asm volatile("fence.proxy.async.shared::cta;\n" ::: "memory");
        }
        __syncthreads();
        if (wid == 0) {
            if (elect_one_pred()) {
                const uint64_t ad = sdesc_sw128(smem_base + s * STAGE_BYTES);
                const uint64_t bd = sdesc_sw128(smem_base + s * STAGE_BYTES + 16384);
#pragma unroll
                for (int kk = 0; kk < 4; kk++)
                    mma_f16_ss(tmem_base, ad + kk * 2, bd + kk * 2, MMA_IDESC,
                               (unsigned)((c | kk) != 0));
                TCGEN05_COMMIT(mbar0 + 8 * s);
            }
        }
    }

    if (wid == 0) {
        if (elect_one_pred()) TCGEN05_COMMIT(mbar_done);
    }
    MBARRIER_WAIT_PARITY(mbar_done, 0);
    TCGEN05_FENCE_AFTER();

    // ---- epilogue: LDTM -> smem -> fused LSTM cell ----
    {
        uint32_t regs[64];
        const uint32_t cb = (uint32_t)(wid >> 2) * 64;   // col half: warps 0-3 -> 0, 4-7 -> 64
        TCGEN05_LD_X32(regs, tmem_base + cb);
        TCGEN05_LD_X32(regs + 32, tmem_base + cb + 32);
        TCGEN05_WAIT_LD();
        TCGEN05_FENCE_BEFORE();

        float* zs = (float*)sm;   // [128][133]
        const int row = (wid & 3) * 32 + lane;
#pragma unroll
        for (int c2 = 0; c2 < 64; c2++)
            zs[row * 133 + cb + c2] = __uint_as_float(regs[c2]);
        __syncthreads();

        const int hb = nt * 32;
        for (int e = tid; e < 128 * 32; e += 256) {
            const int r = e >> 5;
            const int hc = e & 31;
            float zi = zs[r * 133 + hc]      + bias[hb + hc];
            float zj = zs[r * 133 + 32 + hc] + bias[HH + hb + hc];
            float zf = zs[r * 133 + 64 + hc] + bias[2 * HH + hb + hc];
            float zo = zs[r * 133 + 96 + hc] + bias[3 * HH + hb + hc];
            const int gi = (m0 + r) * HH + hb + hc;
            float cc = cst[gi];
            float ncell = cc * sigmoidf_(zf + 1.f) + sigmoidf_(zi) * tanhf(zj);
            hout[gi] = __float2bfloat16(tanhf(ncell) * sigmoidf_(zo));
            cst[gi] = ncell;
        }
    }

    __syncthreads();
    if (wid == 0) {
        TCGEN05_RELINQUISH();
        TCGEN05_DEALLOC(tmem_base, 128);
    }
#endif // HAS_TCGEN05
}

// ============================================================================
// Fallback: mma.sync (HMMA) fused step kernel — round-1 proven path.
// Block tile: 64 rows (batch) x 32 H-cols -> z tile 64 x 128 (4 gates x 32 cols).
// ============================================================================
#define AS_STRIDE 40    // 32 + 8 pad (bf16)
#define BS_STRIDE 136   // 128 + 8 pad (bf16)
#define ZS_STRIDE 132   // 128 + 4 pad (float)

__global__ __launch_bounds__(256, 1)
void lstm_step_fb(int layer, int t, int pin, const float* __restrict__ bias) {
    __shared__ __align__(16) unsigned char smem_raw[64 * ZS_STRIDE * 4]; // 33792 B
    __nv_bfloat16* As = (__nv_bfloat16*)smem_raw;                 // [2][64][AS_STRIDE]
    __nv_bfloat16* Bs = (__nv_bfloat16*)(smem_raw + 10240);       // [2][32][BS_STRIDE]
    float* zs = (float*)smem_raw;                                 // [64][ZS_STRIDE]

    int K, boundk, lda0;
    const __nv_bfloat16 *A0, *A1, *Wm;
    float* cst;
    __nv_bfloat16* hout;
    const int pout = pin ^ 1;

    if (layer == 0) {
        K = K1; boundk = DD; lda0 = DD;
        A0 = g_X + (size_t)t * BB * DD;
        A1 = g_h1[pin];
        Wm = g_W1; cst = g_c1; hout = g_h1[pout];
    } else {
        K = K2; boundk = HH; lda0 = HH;
        A0 = g_h1[pout];
        A1 = g_h2[pin];
        Wm = g_W2; cst = g_c2; hout = g_h2[pout];
    }

    const int n0 = blockIdx.x * 32;
    const int m0 = blockIdx.y * 64;
    const int tid = threadIdx.x;
    const int lane = tid & 31;
    const int wid = tid >> 5;
    const int wm = wid & 3;
    const int wn = wid >> 2;

    const int rowA = tid >> 2;
    const int quadA = tid & 3;

    float acc[8][4];
#pragma unroll
    for (int j = 0; j < 8; j++)
#pragma unroll
        for (int q = 0; q < 4; q++) acc[j][q] = 0.f;

    auto load_stage = [&](int kt, int s) {
        const int k0 = kt * 32;
        const __nv_bfloat16* gpA;
        if (k0 < boundk) gpA = A0 + (size_t)(m0 + rowA) * lda0 + k0 + quadA * 8;
        else             gpA = A1 + (size_t)(m0 + rowA) * HH + (k0 - boundk) + quadA * 8;
        uint32_t dstA = smem_u32(As + s * 64 * AS_STRIDE + rowA * AS_STRIDE + quadA * 8);
        asm volatile("cp.async.cg.shared.global [%0], [%1], 16;\n" :: "r"(dstA), "l"(gpA));
#pragma unroll
        for (int i = 0; i < 2; i++) {
            int c = tid + i * 256;
            int kk = c >> 4;
            int ncv = (c & 15) * 8;
            int g = ncv >> 5;
            int col = g * HH + n0 + (ncv & 31);
            const __nv_bfloat16* gpB = Wm + (size_t)(k0 + kk) * FOURH + col;
            uint32_t dstB = smem_u32(Bs + s * 32 * BS_STRIDE + kk * BS_STRIDE + ncv);
            asm volatile("cp.async.cg.shared.global [%0], [%1], 16;\n" :: "r"(dstB), "l"(gpB));
        }
    };

    load_stage(0, 0);
    asm volatile("cp.async.commit_group;\n" ::: "memory");

    const int nK = K >> 5;
    for (int kt = 0; kt < nK; ++kt) {
        const int s = kt & 1;
        if (kt + 1 < nK) load_stage(kt + 1, s ^ 1);
        asm volatile("cp.async.commit_group;\n" ::: "memory");
        asm volatile("cp.async.wait_group 1;\n" ::: "memory");
        __syncthreads();

#pragma unroll
        for (int ks = 0; ks < 2; ++ks) {
            uint32_t a0, a1, a2, a3;
            {
                int row = wm * 16 + (lane & 15);
                int colb = ks * 16 + (lane >> 4) * 8;
                uint32_t addr = smem_u32(As + s * 64 * AS_STRIDE + row * AS_STRIDE + colb);
                asm volatile("ldmatrix.sync.aligned.m8n8.x4.shared.b16 {%0,%1,%2,%3}, [%4];\n"
                             : "=r"(a0), "=r"(a1), "=r"(a2), "=r"(a3) : "r"(addr));
            }
#pragma unroll
            for (int j2 = 0; j2 < 4; j2++) {
                uint32_t b0, b1, b2, b3;
                int krow = ks * 16 + (lane & 7) + ((lane >> 3) & 1) * 8;
                int ncol = wn * 64 + j2 * 16 + (lane >> 4) * 8;
                uint32_t addr = smem_u32(Bs + s * 32 * BS_STRIDE + krow * BS_STRIDE + ncol);
                asm volatile("ldmatrix.sync.aligned.m8n8.x4.trans.shared.b16 {%0,%1,%2,%3}, [%4];\n"
                             : "=r"(b0), "=r"(b1), "=r"(b2), "=r"(b3) : "r"(addr));
                asm volatile("mma.sync.aligned.m16n8k16.row.col.f32.bf16.bf16.f32 "
                             "{%0,%1,%2,%3}, {%4,%5,%6,%7}, {%8,%9}, {%0,%1,%2,%3};\n"
                             : "+f"(acc[2 * j2][0]), "+f"(acc[2 * j2][1]),
                               "+f"(acc[2 * j2][2]), "+f"(acc[2 * j2][3])
                             : "r"(a0), "r"(a1), "r"(a2), "r"(a3), "r"(b0), "r"(b1));
                asm volatile("mma.sync.aligned.m16n8k16.row.col.f32.bf16.bf16.f32 "
                             "{%0,%1,%2,%3}, {%4,%5,%6,%7}, {%8,%9}, {%0,%1,%2,%3};\n"
                             : "+f"(acc[2 * j2 + 1][0]), "+f"(acc[2 * j2 + 1][1]),
                               "+f"(acc[2 * j2 + 1][2]), "+f"(acc[2 * j2 + 1][3])
                             : "r"(a0), "r"(a1), "r"(a2), "r"(a3), "r"(b2), "r"(b3));
            }
        }
        __syncthreads();
    }

#pragma unroll
    for (int j = 0; j < 8; j++) {
        int col = wn * 64 + j * 8 + (lane & 3) * 2;
        int r = wm * 16 + (lane >> 2);
        zs[r * ZS_STRIDE + col]           = acc[j][0];
        zs[r * ZS_STRIDE + col + 1]       = acc[j][1];
        zs[(r + 8) * ZS_STRIDE + col]     = acc[j][2];
        zs[(r + 8) * ZS_STRIDE + col + 1] = acc[j][3];
    }
    __syncthreads();

#pragma unroll
    for (int e = tid; e < 64 * 32; e += 256) {
        int r = e >> 5;
        int hc = e & 31;
        float zi = zs[r * ZS_STRIDE + hc]        + bias[0 * HH + n0 + hc];
        float zj = zs[r * ZS_STRIDE + 32 + hc]   + bias[1 * HH + n0 + hc];
        float zf = zs[r * ZS_STRIDE + 64 + hc]   + bias[2 * HH + n0 + hc];
        float zo = zs[r * ZS_STRIDE + 96 + hc]   + bias[3 * HH + n0 + hc];
        int gi = (m0 + r) * HH + n0 + hc;
        float c = cst[gi];
        float ncell = c * sigmoidf_(zf + 1.f) + sigmoidf_(zi) * tanhf(zj);
        float nh = tanhf(ncell) * sigmoidf_(zo);
        cst[gi] = ncell;
        hout[gi] = __float2bfloat16(nh);
    }
}

// ---------------- dense head + loss ----------------
__global__ void head_kernel(const float* __restrict__ Wd, const float* __restrict__ bd,
                            const float* __restrict__ labels) {
    const int b = blockIdx.x;
    const int lane = threadIdx.x & 31;
    const int w = threadIdx.x >> 5;
    const __nv_bfloat16* h = g_h2[0];  // T=336 even -> final h2 in slot 0
    __shared__ float warpsum[8];
    float total = 0.f;
    for (int l = w; l < 24; l += 8) {
        float s = 0.f;
        for (int k = lane; k < HH; k += 32)
            s += __bfloat162float(h[b * HH + k]) * Wd[k * 24 + l];
#pragma unroll
        for (int off = 16; off; off >>= 1) s += __shfl_xor_sync(0xffffffffu, s, off);
        if (lane == 0) {
            float pred = s + bd[l];
            float e = pred - labels[b * 24 + l];
            total += e * e;
        }
    }
    if (lane == 0) warpsum[w] = total;
    __syncthreads();
    if (threadIdx.x == 0) {
        float acc = 0.f;
#pragma unroll
        for (int i = 0; i < 8; i++) acc += warpsum[i];
        g_partial[b] = acc;
    }
}

__global__ void finish_kernel(float* __restrict__ out) {
    __shared__ float sh[256];
    sh[threadIdx.x] = g_partial[threadIdx.x];
    __syncthreads();
    for (int s = 128; s; s >>= 1) {
        if (threadIdx.x < s) sh[threadIdx.x] += sh[threadIdx.x + s];
        __syncthreads();
    }
    if (threadIdx.x == 0) out[0] = sh[0] / (float)(BB * 24);
}

// ---------------- launch ----------------
extern "C" void kernel_launch(void* const* d_in, const int* in_sizes, int n_in,
                              void* d_out, int out_size) {
    const float* features = (const float*)d_in[0];
    const float* labels   = (const float*)d_in[1];
    const float* W1       = (const float*)d_in[2];
    const float* b1       = (const float*)d_in[3];
    const float* W2       = (const float*)d_in[4];
    const float* b2       = (const float*)d_in[5];
    const float* Wd       = (const float*)d_in[6];
    const float* bd       = (const float*)d_in[7];
    float* out = (float*)d_out;

    // Dispatch: did the loaded binary get the real tcgen05 kernel?
    // The compiled-out stub uses ~2-10 regs; the real kernel holds >=64
    // (regs[64] epilogue). Deterministic, no stream ops, capture-safe.
    static int use_tc = -1;
    if (use_tc < 0) {
        cudaFuncAttributes attr{};
        cudaFuncGetAttributes(&attr, lstm_step_tc);
        use_tc = (attr.numRegs > 40) ? 1 : 0;
        if (use_tc) {
            cudaFuncSetAttribute(lstm_step_tc,
                                 cudaFuncAttributeMaxDynamicSharedMemorySize, SMEM_DYN);
        }
    }

    if (use_tc) {
        conv_w_t<<<dim3(K1 / 32, 32, 4), dim3(32, 8)>>>(W1, 0, K1);
        conv_w_t<<<dim3(K2 / 32, 32, 4), dim3(32, 8)>>>(W2, 1, K2);
    } else {
        conv_w_kernel<<<592, 256>>>(W1, 0, K1 * FOURH);
        conv_w_kernel<<<592, 256>>>(W2, 1, K2 * FOURH);
    }
    conv_x_kernel<<<592, 256>>>(features);
    init_state_kernel<<<512, 256>>>();

    if (use_tc) {
        dim3 grid(32, 2);
        for (int t = 0; t < TT; t++) {
            int p = t & 1;
            lstm_step_tc<<<grid, 256, SMEM_DYN>>>(0, t, p, b1);
            lstm_step_tc<<<grid, 256, SMEM_DYN>>>(1, t, p, b2);
        }
    } else {
        dim3 grid(32, 4);
        for (int t = 0; t < TT; t++) {
            int p = t & 1;
            lstm_step_fb<<<grid, 256>>>(0, t, p, b1);
            lstm_step_fb<<<grid, 256>>>(1, t, p, b2);
        }
    }

    head_kernel<<<BB, 256>>>(Wd, bd, labels);
    finish_kernel<<<1, 256>>>(out);
}

// round 4
// speedup vs baseline: 1.3230x; 1.0831x over previous
#include <cuda_runtime.h>
#include <cuda_bf16.h>
#include <cstdint>

#define BB 256
#define TT 336
#define DD 128
#define HH 1024
#define K1 1152
#define K2 2048
#define FOURH 4096

#define STAGES 5
#define PRE 3
#define STAGE_BYTES 32768         // A tile 16KB + B tile 16KB
#define SMEM_DYN (STAGES * STAGE_BYTES + 1024)
#define NCTA 64

// ---- arch-feature gate: tcgen05 only exists on the 'a' / family-specific targets ----
#if defined(__CUDA_ARCH__) && \
    (defined(__CUDA_ARCH_FEAT_SM103_ALL) || defined(__CUDA_ARCH_FEAT_SM100_ALL) || \
     (defined(__CUDA_ARCH_SPECIFIC__) && (__CUDA_ARCH_SPECIFIC__ >= 1000)) || \
     (defined(__CUDA_ARCH_FAMILY_SPECIFIC__) && (__CUDA_ARCH_FAMILY_SPECIFIC__ >= 1000)))
#define HAS_TCGEN05 1
#else
#define HAS_TCGEN05 0
#endif

// ---------------- device-global scratch ----------------
__device__ __nv_bfloat16 g_W1[K1 * FOURH];   // tc: [nt*128+g*32+c][K]; fb: [k][4096]
__device__ __nv_bfloat16 g_W2[K2 * FOURH];
__device__ __nv_bfloat16 g_X[TT * BB * DD];  // [t][b][d]
__device__ __nv_bfloat16 g_h1[2][BB * HH];
__device__ __nv_bfloat16 g_h2[2][BB * HH];
__device__ float g_c1[BB * HH];
__device__ float g_c2[BB * HH];
__device__ float g_partial[BB];
__device__ unsigned g_bar_ctr;

// ---------------- helpers ----------------
__device__ __forceinline__ uint32_t smem_u32(const void* p) {
    return (uint32_t)__cvta_generic_to_shared(p);
}
__device__ __forceinline__ float fast_tanh(float x) {
    float y;
    asm("tanh.approx.f32 %0, %1;" : "=f"(y) : "f"(x));
    return y;
}
__device__ __forceinline__ float fast_sigmoid(float x) {
    return 0.5f * fast_tanh(0.5f * x) + 0.5f;
}
__device__ __forceinline__ float sigmoidf_(float x) { return 1.f / (1.f + __expf(-x)); }

// ---------------- conversion / init kernels ----------------
__global__ void conv_w_t(const float* __restrict__ src, int which, int K) {
    __shared__ float tile[32][33];
    const int kb = blockIdx.x * 32, nt = blockIdx.y, g = blockIdx.z;
    const int tx = threadIdx.x, ty0 = threadIdx.y;
#pragma unroll
    for (int i = 0; i < 4; i++) {
        int ty = ty0 + i * 8;
        tile[ty][tx] = src[(size_t)(kb + ty) * FOURH + g * HH + nt * 32 + tx];
    }
    __syncthreads();
    __nv_bfloat16* dst = (which == 0) ? g_W1 : g_W2;
#pragma unroll
    for (int i = 0; i < 4; i++) {
        int ty = ty0 + i * 8;
        dst[(size_t)(nt * 128 + g * 32 + ty) * K + kb + tx] = __float2bfloat16(tile[tx][ty]);
    }
}

__global__ void conv_w_kernel(const float* __restrict__ src, int which, int n) {
    for (int i = blockIdx.x * blockDim.x + threadIdx.x; i < n; i += gridDim.x * blockDim.x) {
        __nv_bfloat16 v = __float2bfloat16(src[i]);
        if (which == 0) g_W1[i] = v;
        else            g_W2[i] = v;
    }
}

__global__ void conv_x_kernel(const float* __restrict__ f) {
    int n = BB * TT * DD;
    for (int i = blockIdx.x * blockDim.x + threadIdx.x; i < n; i += gridDim.x * blockDim.x) {
        int b = i / (TT * DD);
        int r = i % (TT * DD);
        int t = r / DD;
        int d = r % DD;
        g_X[(size_t)t * BB * DD + b * DD + d] = __float2bfloat16(f[i]);
    }
}

__global__ void init_state_kernel() {
    int n = BB * HH;
    __nv_bfloat16 z = __float2bfloat16(0.f);
    if (blockIdx.x == 0 && threadIdx.x == 0) g_bar_ctr = 0;
    for (int i = blockIdx.x * blockDim.x + threadIdx.x; i < n; i += gridDim.x * blockDim.x) {
        g_c1[i] = 0.f;
        g_c2[i] = 0.f;
        g_h1[0][i] = z;
        g_h2[0][i] = z;
    }
}

// ============================================================================
// tcgen05 PTX helpers ('a'-variant targets only)
// ============================================================================
#if HAS_TCGEN05

__device__ __forceinline__ uint32_t elect_one_pred() {
    uint32_t pred;
    asm volatile(
        "{\n\t.reg .pred p;\n\t"
        "elect.sync _|p, 0xFFFFFFFF;\n\t"
        "selp.b32 %0, 1, 0, p;\n\t}"
        : "=r"(pred));
    return pred;
}

#define MBARRIER_INIT(mbar, count) \
    asm volatile("mbarrier.init.shared.b64 [%0], %1;" :: "r"((uint32_t)(mbar)), "r"((uint32_t)(count)) : "memory")

#define MBARRIER_WAIT_PARITY(mbar_addr, phase_parity) do {                          \
    uint32_t _mbar = (uint32_t)(mbar_addr);                                         \
    uint32_t _parity = (uint32_t)(phase_parity);                                    \
    uint32_t _done;                                                                 \
    asm volatile(                                                                   \
        "{\n\t.reg .pred p;\n\t"                                                    \
        "mbarrier.try_wait.parity.acquire.cta.shared::cta.b64 p, [%1], %2;\n\t"     \
        "selp.b32 %0, 1, 0, p;\n\t}"                                                \
        : "=r"(_done) : "r"(_mbar), "r"(_parity) : "memory");                       \
    if (!_done) {                                                                   \
        asm volatile(                                                               \
            "{\n\t.reg .pred P1;\n\t"                                               \
            "WAIT_LOOP_%=:\n\t"                                                     \
            "mbarrier.try_wait.parity.acquire.cta.shared::cta.b64 P1, [%0], %1, 0x989680;\n\t" \
            "@P1 bra.uni WAIT_DONE_%=;\n\t"                                         \
            "bra.uni WAIT_LOOP_%=;\n\t"                                             \
            "WAIT_DONE_%=:\n\t}"                                                    \
            :: "r"(_mbar), "r"(_parity) : "memory");                                \
    }                                                                               \
} while (0)

#define TCGEN05_ALLOC(smem_result_addr, nCols) \
    asm volatile("tcgen05.alloc.cta_group::1.sync.aligned.shared::cta.b32 [%0], %1;" \
                 :: "r"((uint32_t)(smem_result_addr)), "r"((uint32_t)(nCols)) : "memory")
#define TCGEN05_DEALLOC(tmem_addr, nCols) \
    asm volatile("tcgen05.dealloc.cta_group::1.sync.aligned.b32 %0, %1;" \
                 :: "r"(tmem_addr), "r"((uint32_t)(nCols)))
#define TCGEN05_RELINQUISH() \
    asm volatile("tcgen05.relinquish_alloc_permit.cta_group::1.sync.aligned;")
#define TCGEN05_COMMIT(mbar_addr) \
    asm volatile("tcgen05.commit.cta_group::1.mbarrier::arrive::one.shared::cluster.b64 [%0];" \
                 :: "r"((uint32_t)(mbar_addr)) : "memory")
#define TCGEN05_WAIT_LD()  asm volatile("tcgen05.wait::ld.sync.aligned;" ::: "memory")
#define TCGEN05_FENCE_AFTER()  asm volatile("tcgen05.fence::after_thread_sync;" ::: "memory")
#define TCGEN05_FENCE_BEFORE() asm volatile("tcgen05.fence::before_thread_sync;" ::: "memory")

#define TCGEN05_LD_X32(r, tmem_addr) \
    asm volatile( \
        "tcgen05.ld.sync.aligned.32x32b.x32.b32 " \
        "{%0, %1, %2, %3, %4, %5, %6, %7, " \
        " %8, %9, %10, %11, %12, %13, %14, %15, " \
        " %16, %17, %18, %19, %20, %21, %22, %23, " \
        " %24, %25, %26, %27, %28, %29, %30, %31}, [%32];" \
        : "=r"((r)[0]),  "=r"((r)[1]),  "=r"((r)[2]),  "=r"((r)[3]), \
          "=r"((r)[4]),  "=r"((r)[5]),  "=r"((r)[6]),  "=r"((r)[7]), \
          "=r"((r)[8]),  "=r"((r)[9]),  "=r"((r)[10]), "=r"((r)[11]), \
          "=r"((r)[12]), "=r"((r)[13]), "=r"((r)[14]), "=r"((r)[15]), \
          "=r"((r)[16]), "=r"((r)[17]), "=r"((r)[18]), "=r"((r)[19]), \
          "=r"((r)[20]), "=r"((r)[21]), "=r"((r)[22]), "=r"((r)[23]), \
          "=r"((r)[24]), "=r"((r)[25]), "=r"((r)[26]), "=r"((r)[27]), \
          "=r"((r)[28]), "=r"((r)[29]), "=r"((r)[30]), "=r"((r)[31]) \
        : "r"(tmem_addr))

__device__ __forceinline__ uint64_t sdesc_sw128(uint32_t addr) {
    return (2ULL << 61) | (1ULL << 46) | (64ULL << 32) | (1ULL << 16) |
           (uint64_t)((addr >> 4) & 0x3FFF);
}

// idesc kind::f16: dtype=F32, atype=btype=BF16, N=128, M=128
#define MMA_IDESC ((1u << 4) | (1u << 7) | (1u << 10) | ((128u / 8) << 17) | ((128u / 16) << 24))

__device__ __forceinline__ void mma_f16_ss(uint32_t d, uint64_t ad, uint64_t bd,
                                           uint32_t idesc, unsigned en) {
    asm volatile(
        "{\n\t.reg .pred p;\n\t"
        "setp.ne.u32 p, %5, 0;\n\t"
        "tcgen05.mma.cta_group::1.kind::f16 [%0], %1, %2, %3, {%4, %4, %4, %4}, p;\n\t}"
        :: "r"(d), "l"(ad), "l"(bd), "r"(idesc), "r"(0u), "r"(en) : "memory");
}

#endif // HAS_TCGEN05

// ============================================================================
// PERSISTENT tcgen05 kernel: all 336 steps x 2 layers in one launch.
// 64 CTAs (one wave, co-resident), grid barrier between layers.
// CTA tile: M=128 batch x N=128 z-cols. warp0 = MMA issuer, warps 1-7 loaders.
// ============================================================================
__global__ __launch_bounds__(256, 1)
void lstm_persist(const float* __restrict__ b1, const float* __restrict__ b2) {
#if HAS_TCGEN05
    extern __shared__ __align__(1024) unsigned char sm[];
    const uint32_t smem_base = smem_u32(sm);
    const int tid = threadIdx.x;
    const int wid = tid >> 5;
    const int lane = tid & 31;
    const int nt = blockIdx.x >> 1;
    const int m0 = (blockIdx.x & 1) * 128;

    const uint32_t ctrl = smem_base + STAGES * STAGE_BYTES;   // tmem ptr
    const uint32_t mbar0 = ctrl + 16;                          // ring mbars
    const uint32_t mbar_done = ctrl + 16 + 8 * STAGES;

    if (wid == 0) TCGEN05_ALLOC(ctrl, 128);
    if (tid == 0) {
#pragma unroll
        for (int s = 0; s < STAGES; s++) MBARRIER_INIT(mbar0 + 8 * s, 1);
        MBARRIER_INIT(mbar_done, 1);
    }
    __syncthreads();
    uint32_t tmem_base;
    asm volatile("ld.shared.b32 %0, [%1];" : "=r"(tmem_base) : "r"(ctrl));

    int ph[STAGES];
#pragma unroll
    for (int s = 0; s < STAGES; s++) ph[s] = 0;
    int done_par = 0;
    unsigned gj = 0;       // running global chunk counter (ring phase continuity)
    unsigned bar_n = 0;    // grid-barrier count

    for (int t = 0; t < TT; t++) {
        const int pin = t & 1;
        const int pout = pin ^ 1;
#pragma unroll 1
        for (int layer = 0; layer < 2; layer++) {
            int K, nc, boundk, lda0;
            const __nv_bfloat16 *A0, *A1, *Wp;
            float* cst;
            __nv_bfloat16* hout;
            const float* bias;
            if (layer == 0) {
                K = K1; nc = K1 / 64; boundk = DD; lda0 = DD;
                A0 = g_X + t * BB * DD; A1 = g_h1[pin];
                Wp = g_W1; cst = g_c1; hout = g_h1[pout]; bias = b1;
            } else {
                K = K2; nc = K2 / 64; boundk = HH; lda0 = HH;
                A0 = g_h1[pout]; A1 = g_h2[pin];
                Wp = g_W2; cst = g_c2; hout = g_h2[pout]; bias = b2;
            }

            auto load_chunk = [&](int c) {
                const unsigned G = gj + c;
                const int s = G % STAGES;
                const uint32_t sbase = smem_base + s * STAGE_BYTES;
                const int k0 = c * 64;
                const __nv_bfloat16* Abase;
                int lda;
                if (k0 < boundk) { Abase = A0 + k0; lda = lda0; }
                else             { Abase = A1 + (k0 - boundk); lda = HH; }
                for (int idx = tid - 32; idx < 2048; idx += 224) {
                    const int half = idx >> 10;          // 0=A, 1=B
                    const int r = (idx & 1023) >> 3;     // row 0..127
                    const int ch = idx & 7;              // 16B chunk in 128B row
                    const __nv_bfloat16* gp;
                    if (half == 0) gp = Abase + (m0 + r) * lda + ch * 8;
                    else           gp = Wp + (size_t)(nt * 128 + r) * K + k0 + ch * 8;
                    uint32_t off = (r << 7) | (ch << 4);
                    uint32_t sw = off ^ ((off >> 3) & 0x70);
                    uint32_t dst = sbase + (half << 14) + sw;
                    asm volatile("cp.async.cg.shared.global [%0], [%1], 16;\n" :: "r"(dst), "l"(gp));
                }
            };
            auto wait_ring = [&](int c) {
                const unsigned G = gj + c;
                if (G >= STAGES) {
                    const int s = G % STAGES;
                    MBARRIER_WAIT_PARITY(mbar0 + 8 * s, ph[s]);
                    ph[s] ^= 1;
                }
            };

            if (wid > 0) {
#pragma unroll
                for (int j = 0; j < PRE; j++) {
                    wait_ring(j);
                    load_chunk(j);
                    asm volatile("cp.async.commit_group;\n" ::: "memory");
                }
            }

            for (int c = 0; c < nc; ++c) {
                const int s = (int)((gj + c) % STAGES);
                if (wid > 0) {
                    const int j = c + PRE;
                    if (j < nc) {
                        wait_ring(j);
                        load_chunk(j);
                    }
                    asm volatile("cp.async.commit_group;\n" ::: "memory");
                    asm volatile("cp.async.wait_group %0;\n" :: "n"(PRE) : "memory");
                    asm volatile("fence.proxy.async.shared::cta;\n" ::: "memory");
                }
                __syncthreads();
                if (wid == 0) {
                    if (elect_one_pred()) {
                        const uint64_t ad = sdesc_sw128(smem_base + s * STAGE_BYTES);
                        const uint64_t bd = sdesc_sw128(smem_base + s * STAGE_BYTES + 16384);
#pragma unroll
                        for (int kk = 0; kk < 4; kk++)
                            mma_f16_ss(tmem_base, ad + kk * 2, bd + kk * 2, MMA_IDESC,
                                       (unsigned)((c | kk) != 0));
                        TCGEN05_COMMIT(mbar0 + 8 * s);
                    }
                }
            }

            if (wid == 0) {
                if (elect_one_pred()) TCGEN05_COMMIT(mbar_done);
            }
            MBARRIER_WAIT_PARITY(mbar_done, done_par);
            done_par ^= 1;
            TCGEN05_FENCE_AFTER();

            // ---- epilogue: LDTM -> smem -> fused LSTM cell ----
            {
                uint32_t regs[64];
                const uint32_t cb = (uint32_t)(wid >> 2) * 64;
                TCGEN05_LD_X32(regs, tmem_base + cb);
                TCGEN05_LD_X32(regs + 32, tmem_base + cb + 32);
                TCGEN05_WAIT_LD();
                TCGEN05_FENCE_BEFORE();

                float* zs = (float*)sm;   // [128][133] over stage smem (pipeline drained)
                const int row = (wid & 3) * 32 + lane;
#pragma unroll
                for (int c2 = 0; c2 < 64; c2++)
                    zs[row * 133 + cb + c2] = __uint_as_float(regs[c2]);
                __syncthreads();

                const int hb = nt * 32;
                for (int e = tid; e < 128 * 32; e += 256) {
                    const int r = e >> 5;
                    const int hc = e & 31;
                    float zi = zs[r * 133 + hc]      + bias[hb + hc];
                    float zj = zs[r * 133 + 32 + hc] + bias[HH + hb + hc];
                    float zf = zs[r * 133 + 64 + hc] + bias[2 * HH + hb + hc];
                    float zo = zs[r * 133 + 96 + hc] + bias[3 * HH + hb + hc];
                    const int gi = (m0 + r) * HH + hb + hc;
                    float cc = cst[gi];
                    float ncell = cc * fast_sigmoid(zf + 1.f) +
                                  fast_sigmoid(zi) * fast_tanh(zj);
                    hout[gi] = __float2bfloat16(fast_tanh(ncell) * fast_sigmoid(zo));
                    cst[gi] = ncell;
                }
            }

            gj += (unsigned)nc;

            // ---- grid barrier: h visible to all CTAs before next layer ----
            bar_n++;
            __syncthreads();
            if (tid == 0) {
                __threadfence();
                atomicAdd(&g_bar_ctr, 1u);
                const unsigned tgt = bar_n * NCTA;
                while (*(volatile unsigned*)&g_bar_ctr < tgt) { }
            }
            __syncthreads();
        }
    }

    if (wid == 0) {
        TCGEN05_RELINQUISH();
        TCGEN05_DEALLOC(tmem_base, 128);
    }
#endif // HAS_TCGEN05
}

// ============================================================================
// Fallback: mma.sync (HMMA) fused step kernel (round-1 proven path).
// ============================================================================
#define AS_STRIDE 40
#define BS_STRIDE 136
#define ZS_STRIDE 132

__global__ __launch_bounds__(256, 1)
void lstm_step_fb(int layer, int t, int pin, const float* __restrict__ bias) {
    __shared__ __align__(16) unsigned char smem_raw[64 * ZS_STRIDE * 4];
    __nv_bfloat16* As = (__nv_bfloat16*)smem_raw;
    __nv_bfloat16* Bs = (__nv_bfloat16*)(smem_raw + 10240);
    float* zs = (float*)smem_raw;

    int K, boundk, lda0;
    const __nv_bfloat16 *A0, *A1, *Wm;
    float* cst;
    __nv_bfloat16* hout;
    const int pout = pin ^ 1;

    if (layer == 0) {
        K = K1; boundk = DD; lda0 = DD;
        A0 = g_X + (size_t)t * BB * DD;
        A1 = g_h1[pin];
        Wm = g_W1; cst = g_c1; hout = g_h1[pout];
    } else {
        K = K2; boundk = HH; lda0 = HH;
        A0 = g_h1[pout];
        A1 = g_h2[pin];
        Wm = g_W2; cst = g_c2; hout = g_h2[pout];
    }

    const int n0 = blockIdx.x * 32;
    const int m0 = blockIdx.y * 64;
    const int tid = threadIdx.x;
    const int lane = tid & 31;
    const int wid = tid >> 5;
    const int wm = wid & 3;
    const int wn = wid >> 2;
    const int rowA = tid >> 2;
    const int quadA = tid & 3;

    float acc[8][4];
#pragma unroll
    for (int j = 0; j < 8; j++)
#pragma unroll
        for (int q = 0; q < 4; q++) acc[j][q] = 0.f;

    auto load_stage = [&](int kt, int s) {
        const int k0 = kt * 32;
        const __nv_bfloat16* gpA;
        if (k0 < boundk) gpA = A0 + (size_t)(m0 + rowA) * lda0 + k0 + quadA * 8;
        else             gpA = A1 + (size_t)(m0 + rowA) * HH + (k0 - boundk) + quadA * 8;
        uint32_t dstA = smem_u32(As + s * 64 * AS_STRIDE + rowA * AS_STRIDE + quadA * 8);
        asm volatile("cp.async.cg.shared.global [%0], [%1], 16;\n" :: "r"(dstA), "l"(gpA));
#pragma unroll
        for (int i = 0; i < 2; i++) {
            int c = tid + i * 256;
            int kk = c >> 4;
            int ncv = (c & 15) * 8;
            int g = ncv >> 5;
            int col = g * HH + n0 + (ncv & 31);
            const __nv_bfloat16* gpB = Wm + (size_t)(k0 + kk) * FOURH + col;
            uint32_t dstB = smem_u32(Bs + s * 32 * BS_STRIDE + kk * BS_STRIDE + ncv);
            asm volatile("cp.async.cg.shared.global [%0], [%1], 16;\n" :: "r"(dstB), "l"(gpB));
        }
    };

    load_stage(0, 0);
    asm volatile("cp.async.commit_group;\n" ::: "memory");

    const int nK = K >> 5;
    for (int kt = 0; kt < nK; ++kt) {
        const int s = kt & 1;
        if (kt + 1 < nK) load_stage(kt + 1, s ^ 1);
        asm volatile("cp.async.commit_group;\n" ::: "memory");
        asm volatile("cp.async.wait_group 1;\n" ::: "memory");
        __syncthreads();

#pragma unroll
        for (int ks = 0; ks < 2; ++ks) {
            uint32_t a0, a1, a2, a3;
            {
                int row = wm * 16 + (lane & 15);
                int colb = ks * 16 + (lane >> 4) * 8;
                uint32_t addr = smem_u32(As + s * 64 * AS_STRIDE + row * AS_STRIDE + colb);
                asm volatile("ldmatrix.sync.aligned.m8n8.x4.shared.b16 {%0,%1,%2,%3}, [%4];\n"
                             : "=r"(a0), "=r"(a1), "=r"(a2), "=r"(a3) : "r"(addr));
            }
#pragma unroll
            for (int j2 = 0; j2 < 4; j2++) {
                uint32_t b0, b1, b2, b3;
                int krow = ks * 16 + (lane & 7) + ((lane >> 3) & 1) * 8;
                int ncol = wn * 64 + j2 * 16 + (lane >> 4) * 8;
                uint32_t addr = smem_u32(Bs + s * 32 * BS_STRIDE + krow * BS_STRIDE + ncol);
                asm volatile("ldmatrix.sync.aligned.m8n8.x4.trans.shared.b16 {%0,%1,%2,%3}, [%4];\n"
                             : "=r"(b0), "=r"(b1), "=r"(b2), "=r"(b3) : "r"(addr));
                asm volatile("mma.sync.aligned.m16n8k16.row.col.f32.bf16.bf16.f32 "
                             "{%0,%1,%2,%3}, {%4,%5,%6,%7}, {%8,%9}, {%0,%1,%2,%3};\n"
                             : "+f"(acc[2 * j2][0]), "+f"(acc[2 * j2][1]),
                               "+f"(acc[2 * j2][2]), "+f"(acc[2 * j2][3])
                             : "r"(a0), "r"(a1), "r"(a2), "r"(a3), "r"(b0), "r"(b1));
                asm volatile("mma.sync.aligned.m16n8k16.row.col.f32.bf16.bf16.f32 "
                             "{%0,%1,%2,%3}, {%4,%5,%6,%7}, {%8,%9}, {%0,%1,%2,%3};\n"
                             : "+f"(acc[2 * j2 + 1][0]), "+f"(acc[2 * j2 + 1][1]),
                               "+f"(acc[2 * j2 + 1][2]), "+f"(acc[2 * j2 + 1][3])
                             : "r"(a0), "r"(a1), "r"(a2), "r"(a3), "r"(b2), "r"(b3));
            }
        }
        __syncthreads();
    }

#pragma unroll
    for (int j = 0; j < 8; j++) {
        int col = wn * 64 + j * 8 + (lane & 3) * 2;
        int r = wm * 16 + (lane >> 2);
        zs[r * ZS_STRIDE + col]           = acc[j][0];
        zs[r * ZS_STRIDE + col + 1]       = acc[j][1];
        zs[(r + 8) * ZS_STRIDE + col]     = acc[j][2];
        zs[(r + 8) * ZS_STRIDE + col + 1] = acc[j][3];
    }
    __syncthreads();

#pragma unroll
    for (int e = tid; e < 64 * 32; e += 256) {
        int r = e >> 5;
        int hc = e & 31;
        float zi = zs[r * ZS_STRIDE + hc]        + bias[0 * HH + n0 + hc];
        float zj = zs[r * ZS_STRIDE + 32 + hc]   + bias[1 * HH + n0 + hc];
        float zf = zs[r * ZS_STRIDE + 64 + hc]   + bias[2 * HH + n0 + hc];
        float zo = zs[r * ZS_STRIDE + 96 + hc]   + bias[3 * HH + n0 + hc];
        int gi = (m0 + r) * HH + n0 + hc;
        float c = cst[gi];
        float ncell = c * sigmoidf_(zf + 1.f) + sigmoidf_(zi) * tanhf(zj);
        float nh = tanhf(ncell) * sigmoidf_(zo);
        cst[gi] = ncell;
        hout[gi] = __float2bfloat16(nh);
    }
}

// ---------------- dense head + loss ----------------
__global__ void head_kernel(const float* __restrict__ Wd, const float* __restrict__ bd,
                            const float* __restrict__ labels) {
    const int b = blockIdx.x;
    const int lane = threadIdx.x & 31;
    const int w = threadIdx.x >> 5;
    const __nv_bfloat16* h = g_h2[0];  // T=336 even -> final h2 in slot 0
    __shared__ float warpsum[8];
    float total = 0.f;
    for (int l = w; l < 24; l += 8) {
        float s = 0.f;
        for (int k = lane; k < HH; k += 32)
            s += __bfloat162float(h[b * HH + k]) * Wd[k * 24 + l];
#pragma unroll
        for (int off = 16; off; off >>= 1) s += __shfl_xor_sync(0xffffffffu, s, off);
        if (lane == 0) {
            float pred = s + bd[l];
            float e = pred - labels[b * 24 + l];
            total += e * e;
        }
    }
    if (lane == 0) warpsum[w] = total;
    __syncthreads();
    if (threadIdx.x == 0) {
        float acc = 0.f;
#pragma unroll
        for (int i = 0; i < 8; i++) acc += warpsum[i];
        g_partial[b] = acc;
    }
}

__global__ void finish_kernel(float* __restrict__ out) {
    __shared__ float sh[256];
    sh[threadIdx.x] = g_partial[threadIdx.x];
    __syncthreads();
    for (int s = 128; s; s >>= 1) {
        if (threadIdx.x < s) sh[threadIdx.x] += sh[threadIdx.x + s];
        __syncthreads();
    }
    if (threadIdx.x == 0) out[0] = sh[0] / (float)(BB * 24);
}

// ---------------- launch ----------------
extern "C" void kernel_launch(void* const* d_in, const int* in_sizes, int n_in,
                              void* d_out, int out_size) {
    const float* features = (const float*)d_in[0];
    const float* labels   = (const float*)d_in[1];
    const float* W1       = (const float*)d_in[2];
    const float* b1       = (const float*)d_in[3];
    const float* W2       = (const float*)d_in[4];
    const float* b2       = (const float*)d_in[5];
    const float* Wd       = (const float*)d_in[6];
    const float* bd       = (const float*)d_in[7];
    float* out = (float*)d_out;

    // Dispatch on which binary got the real tcgen05 kernel (stub ~few regs).
    static int use_tc = -1;
    if (use_tc < 0) {
        cudaFuncAttributes attr{};
        cudaFuncGetAttributes(&attr, lstm_persist);
        use_tc = (attr.numRegs > 40) ? 1 : 0;
        if (use_tc) {
            cudaFuncSetAttribute(lstm_persist,
                                 cudaFuncAttributeMaxDynamicSharedMemorySize, SMEM_DYN);
        }
    }

    if (use_tc) {
        conv_w_t<<<dim3(K1 / 32, 32, 4), dim3(32, 8)>>>(W1, 0, K1);
        conv_w_t<<<dim3(K2 / 32, 32, 4), dim3(32, 8)>>>(W2, 1, K2);
    } else {
        conv_w_kernel<<<592, 256>>>(W1, 0, K1 * FOURH);
        conv_w_kernel<<<592, 256>>>(W2, 1, K2 * FOURH);
    }
    conv_x_kernel<<<592, 256>>>(features);
    init_state_kernel<<<512, 256>>>();

    if (use_tc) {
        lstm_persist<<<NCTA, 256, SMEM_DYN>>>(b1, b2);
    } else {
        dim3 grid(32, 4);
        for (int t = 0; t < TT; t++) {
            int p = t & 1;
            lstm_step_fb<<<grid, 256>>>(0, t, p, b1);
            lstm_step_fb<<<grid, 256>>>(1, t, p, b2);
        }
    }

    head_kernel<<<BB, 256>>>(Wd, bd, labels);
    finish_kernel<<<1, 256>>>(out);
}

// round 5
// speedup vs baseline: 1.4100x; 1.0657x over previous
#include <cuda_runtime.h>
#include <cuda_bf16.h>
#include <cstdint>

#define BB 256
#define TT 336
#define DD 128
#define HH 1024
#define K1 1152
#define K2 2048
#define FOURH 4096

#define STAGES 6
#define STAGE_BYTES 32768         // A tile 16KB + B tile 16KB
#define SMEM_DYN (STAGES * STAGE_BYTES + 1024)
#define NCTA 64

// ---- arch-feature gate: tcgen05 only exists on the 'a' / family-specific targets ----
#if defined(__CUDA_ARCH__) && \
    (defined(__CUDA_ARCH_FEAT_SM103_ALL) || defined(__CUDA_ARCH_FEAT_SM100_ALL) || \
     (defined(__CUDA_ARCH_SPECIFIC__) && (__CUDA_ARCH_SPECIFIC__ >= 1000)) || \
     (defined(__CUDA_ARCH_FAMILY_SPECIFIC__) && (__CUDA_ARCH_FAMILY_SPECIFIC__ >= 1000)))
#define HAS_TCGEN05 1
#else
#define HAS_TCGEN05 0
#endif

// ---------------- device-global scratch ----------------
__device__ __nv_bfloat16 g_W1[K1 * FOURH];   // tc: [nt*128+g*32+c][K]; fb: [k][4096]
__device__ __nv_bfloat16 g_W2[K2 * FOURH];
__device__ __nv_bfloat16 g_X[TT * BB * DD];  // [t][b][d]
__device__ __nv_bfloat16 g_h1[2][BB * HH];
__device__ __nv_bfloat16 g_h2[2][BB * HH];
__device__ float g_c1[BB * HH];
__device__ float g_c2[BB * HH];
__device__ float g_partial[BB];
__device__ unsigned g_bar_ctr;

// ---------------- helpers ----------------
__device__ __forceinline__ uint32_t smem_u32(const void* p) {
    return (uint32_t)__cvta_generic_to_shared(p);
}
__device__ __forceinline__ float fast_tanh(float x) {
    float y;
    asm("tanh.approx.f32 %0, %1;" : "=f"(y) : "f"(x));
    return y;
}
__device__ __forceinline__ float fast_sigmoid(float x) {
    return 0.5f * fast_tanh(0.5f * x) + 0.5f;
}
__device__ __forceinline__ float sigmoidf_(float x) { return 1.f / (1.f + __expf(-x)); }

// ---------------- conversion / init kernels ----------------
__global__ void conv_w_t(const float* __restrict__ src, int which, int K) {
    __shared__ float tile[32][33];
    const int kb = blockIdx.x * 32, nt = blockIdx.y, g = blockIdx.z;
    const int tx = threadIdx.x, ty0 = threadIdx.y;
#pragma unroll
    for (int i = 0; i < 4; i++) {
        int ty = ty0 + i * 8;
        tile[ty][tx] = src[(size_t)(kb + ty) * FOURH + g * HH + nt * 32 + tx];
    }
    __syncthreads();
    __nv_bfloat16* dst = (which == 0) ? g_W1 : g_W2;
#pragma unroll
    for (int i = 0; i < 4; i++) {
        int ty = ty0 + i * 8;
        dst[(size_t)(nt * 128 + g * 32 + ty) * K + kb + tx] = __float2bfloat16(tile[tx][ty]);
    }
}

__global__ void conv_w_kernel(const float* __restrict__ src, int which, int n) {
    for (int i = blockIdx.x * blockDim.x + threadIdx.x; i < n; i += gridDim.x * blockDim.x) {
        __nv_bfloat16 v = __float2bfloat16(src[i]);
        if (which == 0) g_W1[i] = v;
        else            g_W2[i] = v;
    }
}

__global__ void conv_x_kernel(const float* __restrict__ f) {
    int n = BB * TT * DD;
    for (int i = blockIdx.x * blockDim.x + threadIdx.x; i < n; i += gridDim.x * blockDim.x) {
        int b = i / (TT * DD);
        int r = i % (TT * DD);
        int t = r / DD;
        int d = r % DD;
        g_X[(size_t)t * BB * DD + b * DD + d] = __float2bfloat16(f[i]);
    }
}

__global__ void init_state_kernel() {
    int n = BB * HH;
    __nv_bfloat16 z = __float2bfloat16(0.f);
    if (blockIdx.x == 0 && threadIdx.x == 0) g_bar_ctr = 0;
    for (int i = blockIdx.x * blockDim.x + threadIdx.x; i < n; i += gridDim.x * blockDim.x) {
        g_c1[i] = 0.f;
        g_c2[i] = 0.f;
        g_h1[0][i] = z;
        g_h2[0][i] = z;
    }
}

// ============================================================================
// tcgen05 PTX helpers ('a'-variant targets only)
// ============================================================================
#if HAS_TCGEN05

__device__ __forceinline__ uint32_t elect_one_pred() {
    uint32_t pred;
    asm volatile(
        "{\n\t.reg .pred p;\n\t"
        "elect.sync _|p, 0xFFFFFFFF;\n\t"
        "selp.b32 %0, 1, 0, p;\n\t}"
        : "=r"(pred));
    return pred;
}

#define MBARRIER_INIT(mbar, count) \
    asm volatile("mbarrier.init.shared.b64 [%0], %1;" :: "r"((uint32_t)(mbar)), "r"((uint32_t)(count)) : "memory")

#define MBARRIER_WAIT_PARITY(mbar_addr, phase_parity) do {                          \
    uint32_t _mbar = (uint32_t)(mbar_addr);                                         \
    uint32_t _parity = (uint32_t)(phase_parity);                                    \
    uint32_t _done;                                                                 \
    asm volatile(                                                                   \
        "{\n\t.reg .pred p;\n\t"                                                    \
        "mbarrier.try_wait.parity.acquire.cta.shared::cta.b64 p, [%1], %2;\n\t"     \
        "selp.b32 %0, 1, 0, p;\n\t}"                                                \
        : "=r"(_done) : "r"(_mbar), "r"(_parity) : "memory");                       \
    if (!_done) {                                                                   \
        asm volatile(                                                               \
            "{\n\t.reg .pred P1;\n\t"                                               \
            "WAIT_LOOP_%=:\n\t"                                                     \
            "mbarrier.try_wait.parity.acquire.cta.shared::cta.b64 P1, [%0], %1, 0x989680;\n\t" \
            "@P1 bra.uni WAIT_DONE_%=;\n\t"                                         \
            "bra.uni WAIT_LOOP_%=;\n\t"                                             \
            "WAIT_DONE_%=:\n\t}"                                                    \
            :: "r"(_mbar), "r"(_parity) : "memory");                                \
    }                                                                               \
} while (0)

// Deferred arrive: fires on full[s] once this thread's prior cp.asyncs complete.
#define CP_ASYNC_MBAR_ARRIVE(mbar) \
    asm volatile("cp.async.mbarrier.arrive.noinc.shared::cta.b64 [%0];" \
                 :: "r"((uint32_t)(mbar)) : "memory")

#define TCGEN05_ALLOC(smem_result_addr, nCols) \
    asm volatile("tcgen05.alloc.cta_group::1.sync.aligned.shared::cta.b32 [%0], %1;" \
                 :: "r"((uint32_t)(smem_result_addr)), "r"((uint32_t)(nCols)) : "memory")
#define TCGEN05_DEALLOC(tmem_addr, nCols) \
    asm volatile("tcgen05.dealloc.cta_group::1.sync.aligned.b32 %0, %1;" \
                 :: "r"(tmem_addr), "r"((uint32_t)(nCols)))
#define TCGEN05_RELINQUISH() \
    asm volatile("tcgen05.relinquish_alloc_permit.cta_group::1.sync.aligned;")
#define TCGEN05_COMMIT(mbar_addr) \
    asm volatile("tcgen05.commit.cta_group::1.mbarrier::arrive::one.shared::cluster.b64 [%0];" \
                 :: "r"((uint32_t)(mbar_addr)) : "memory")
#define TCGEN05_WAIT_LD()  asm volatile("tcgen05.wait::ld.sync.aligned;" ::: "memory")
#define TCGEN05_FENCE_AFTER()  asm volatile("tcgen05.fence::after_thread_sync;" ::: "memory")
#define TCGEN05_FENCE_BEFORE() asm volatile("tcgen05.fence::before_thread_sync;" ::: "memory")

#define TCGEN05_LD_X32(r, tmem_addr) \
    asm volatile( \
        "tcgen05.ld.sync.aligned.32x32b.x32.b32 " \
        "{%0, %1, %2, %3, %4, %5, %6, %7, " \
        " %8, %9, %10, %11, %12, %13, %14, %15, " \
        " %16, %17, %18, %19, %20, %21, %22, %23, " \
        " %24, %25, %26, %27, %28, %29, %30, %31}, [%32];" \
        : "=r"((r)[0]),  "=r"((r)[1]),  "=r"((r)[2]),  "=r"((r)[3]), \
          "=r"((r)[4]),  "=r"((r)[5]),  "=r"((r)[6]),  "=r"((r)[7]), \
          "=r"((r)[8]),  "=r"((r)[9]),  "=r"((r)[10]), "=r"((r)[11]), \
          "=r"((r)[12]), "=r"((r)[13]), "=r"((r)[14]), "=r"((r)[15]), \
          "=r"((r)[16]), "=r"((r)[17]), "=r"((r)[18]), "=r"((r)[19]), \
          "=r"((r)[20]), "=r"((r)[21]), "=r"((r)[22]), "=r"((r)[23]), \
          "=r"((r)[24]), "=r"((r)[25]), "=r"((r)[26]), "=r"((r)[27]), \
          "=r"((r)[28]), "=r"((r)[29]), "=r"((r)[30]), "=r"((r)[31]) \
        : "r"(tmem_addr))

__device__ __forceinline__ uint64_t sdesc_sw128(uint32_t addr) {
    return (2ULL << 61) | (1ULL << 46) | (64ULL << 32) | (1ULL << 16) |
           (uint64_t)((addr >> 4) & 0x3FFF);
}

// idesc kind::f16: dtype=F32, atype=btype=BF16, N=128, M=128
#define MMA_IDESC ((1u << 4) | (1u << 7) | (1u << 10) | ((128u / 8) << 17) | ((128u / 16) << 24))

__device__ __forceinline__ void mma_f16_ss(uint32_t d, uint64_t ad, uint64_t bd,
                                           uint32_t idesc, unsigned en) {
    asm volatile(
        "{\n\t.reg .pred p;\n\t"
        "setp.ne.u32 p, %5, 0;\n\t"
        "tcgen05.mma.cta_group::1.kind::f16 [%0], %1, %2, %3, {%4, %4, %4, %4}, p;\n\t}"
        :: "r"(d), "l"(ad), "l"(bd), "r"(idesc), "r"(0u), "r"(en) : "memory");
}

#endif // HAS_TCGEN05

// ============================================================================
// PERSISTENT warp-specialized tcgen05 kernel: 336 steps x 2 layers, one launch.
// 64 CTAs co-resident; full/empty mbarrier ring, NO syncthreads in mainloop.
// Warp 0 = free-running MMA issuer; warps 1-7 = free-running loaders.
// ============================================================================
__global__ __launch_bounds__(256, 1)
void lstm_persist(const float* __restrict__ b1, const float* __restrict__ b2) {
#if HAS_TCGEN05
    extern __shared__ __align__(1024) unsigned char sm[];
    const uint32_t smem_base = smem_u32(sm);
    const int tid = threadIdx.x;
    const int wid = tid >> 5;
    const int lane = tid & 31;
    const int nt = blockIdx.x >> 1;
    const int m0 = (blockIdx.x & 1) * 128;

    const uint32_t ctrl = smem_base + STAGES * STAGE_BYTES;   // tmem ptr (16B)
    const uint32_t mb_full = ctrl + 16;                        // [STAGES] x 8B
    const uint32_t mb_empty = mb_full + 8 * STAGES;            // [STAGES] x 8B
    const uint32_t mb_done = mb_empty + 8 * STAGES;

    if (wid == 0) TCGEN05_ALLOC(ctrl, 128);
    if (tid == 0) {
#pragma unroll
        for (int s = 0; s < STAGES; s++) {
            MBARRIER_INIT(mb_full + 8 * s, 224);   // 224 loader threads
            MBARRIER_INIT(mb_empty + 8 * s, 1);    // tcgen05.commit
        }
        MBARRIER_INIT(mb_done, 1);
    }
    __syncthreads();
    uint32_t tmem_base;
    asm volatile("ld.shared.b32 %0, [%1];" : "=r"(tmem_base) : "r"(ctrl));

    int phE[STAGES], phF[STAGES];
#pragma unroll
    for (int s = 0; s < STAGES; s++) { phE[s] = 0; phF[s] = 0; }
    int done_par = 0;
    unsigned gj = 0;       // running global chunk counter
    unsigned bar_n = 0;

    for (int t = 0; t < TT; t++) {
        const int pin = t & 1;
        const int pout = pin ^ 1;
#pragma unroll 1
        for (int layer = 0; layer < 2; layer++) {
            int K, nc, boundk, lda0;
            const __nv_bfloat16 *A0, *A1, *Wp;
            float* cst;
            __nv_bfloat16* hout;
            const float* bias;
            if (layer == 0) {
                K = K1; nc = K1 / 64; boundk = DD; lda0 = DD;
                A0 = g_X + t * BB * DD; A1 = g_h1[pin];
                Wp = g_W1; cst = g_c1; hout = g_h1[pout]; bias = b1;
            } else {
                K = K2; nc = K2 / 64; boundk = HH; lda0 = HH;
                A0 = g_h1[pout]; A1 = g_h2[pin];
                Wp = g_W2; cst = g_c2; hout = g_h2[pout]; bias = b2;
            }

            if (wid > 0) {
                // ---------------- producer: free-running loaders ----------------
                for (int c = 0; c < nc; ++c) {
                    const unsigned G = gj + (unsigned)c;
                    const int s = (int)(G % STAGES);
                    if (G >= STAGES) {
                        MBARRIER_WAIT_PARITY(mb_empty + 8 * s, phE[s]);
                        phE[s] ^= 1;
                    }
                    const uint32_t sbase = smem_base + s * STAGE_BYTES;
                    const int k0 = c * 64;
                    const __nv_bfloat16* Abase;
                    int lda;
                    if (k0 < boundk) { Abase = A0 + k0; lda = lda0; }
                    else             { Abase = A1 + (k0 - boundk); lda = HH; }
                    for (int idx = tid - 32; idx < 2048; idx += 224) {
                        const int half = idx >> 10;          // 0=A, 1=B
                        const int r = (idx & 1023) >> 3;     // row 0..127
                        const int ch = idx & 7;              // 16B chunk in 128B row
                        const __nv_bfloat16* gp;
                        if (half == 0) gp = Abase + (m0 + r) * lda + ch * 8;
                        else           gp = Wp + (size_t)(nt * 128 + r) * K + k0 + ch * 8;
                        uint32_t off = (r << 7) | (ch << 4);
                        uint32_t sw = off ^ ((off >> 3) & 0x70);
                        uint32_t dst = sbase + (half << 14) + sw;
                        asm volatile("cp.async.cg.shared.global [%0], [%1], 16;\n" :: "r"(dst), "l"(gp));
                    }
                    CP_ASYNC_MBAR_ARRIVE(mb_full + 8 * s);
                }
            } else {
                // ---------------- consumer: free-running MMA issuer ----------------
                for (int c = 0; c < nc; ++c) {
                    const unsigned G = gj + (unsigned)c;
                    const int s = (int)(G % STAGES);
                    MBARRIER_WAIT_PARITY(mb_full + 8 * s, phF[s]);
                    phF[s] ^= 1;
                    if (elect_one_pred()) {
                        const uint64_t ad = sdesc_sw128(smem_base + s * STAGE_BYTES);
                        const uint64_t bd = sdesc_sw128(smem_base + s * STAGE_BYTES + 16384);
#pragma unroll
                        for (int kk = 0; kk < 4; kk++)
                            mma_f16_ss(tmem_base, ad + kk * 2, bd + kk * 2, MMA_IDESC,
                                       (unsigned)((c | kk) != 0));
                        TCGEN05_COMMIT(mb_empty + 8 * s);
                    }
                }
                if (elect_one_pred()) TCGEN05_COMMIT(mb_done);
            }

            // ---- all warps: wait GEMM completion ----
            MBARRIER_WAIT_PARITY(mb_done, done_par);
            done_par ^= 1;
            TCGEN05_FENCE_AFTER();

            // ---- epilogue: LDTM -> smem -> fused LSTM cell ----
            {
                uint32_t regs[64];
                const uint32_t cb = (uint32_t)(wid >> 2) * 64;
                TCGEN05_LD_X32(regs, tmem_base + cb);
                TCGEN05_LD_X32(regs + 32, tmem_base + cb + 32);
                TCGEN05_WAIT_LD();
                TCGEN05_FENCE_BEFORE();

                float* zs = (float*)sm;   // [128][133] overlays drained stage smem
                const int row = (wid & 3) * 32 + lane;
#pragma unroll
                for (int c2 = 0; c2 < 64; c2++)
                    zs[row * 133 + cb + c2] = __uint_as_float(regs[c2]);
                __syncthreads();

                const int hb = nt * 32;
                for (int e = tid; e < 128 * 32; e += 256) {
                    const int r = e >> 5;
                    const int hc = e & 31;
                    float zi = zs[r * 133 + hc]      + bias[hb + hc];
                    float zj = zs[r * 133 + 32 + hc] + bias[HH + hb + hc];
                    float zf = zs[r * 133 + 64 + hc] + bias[2 * HH + hb + hc];
                    float zo = zs[r * 133 + 96 + hc] + bias[3 * HH + hb + hc];
                    const int gi = (m0 + r) * HH + hb + hc;
                    float cc = cst[gi];
                    float ncell = cc * fast_sigmoid(zf + 1.f) +
                                  fast_sigmoid(zi) * fast_tanh(zj);
                    hout[gi] = __float2bfloat16(fast_tanh(ncell) * fast_sigmoid(zo));
                    cst[gi] = ncell;
                }
            }

            gj += (unsigned)nc;

            // ---- grid barrier: h visible chip-wide before next GEMM ----
            bar_n++;
            __syncthreads();
            if (tid == 0) {
                __threadfence();
                atomicAdd(&g_bar_ctr, 1u);
                const unsigned tgt = bar_n * NCTA;
                while (*(volatile unsigned*)&g_bar_ctr < tgt) { }
            }
            __syncthreads();
        }
    }

    if (wid == 0) {
        TCGEN05_RELINQUISH();
        TCGEN05_DEALLOC(tmem_base, 128);
    }
#endif // HAS_TCGEN05
}

// ============================================================================
// Fallback: mma.sync (HMMA) fused step kernel (round-1 proven path).
// ============================================================================
#define AS_STRIDE 40
#define BS_STRIDE 136
#define ZS_STRIDE 132

__global__ __launch_bounds__(256, 1)
void lstm_step_fb(int layer, int t, int pin, const float* __restrict__ bias) {
    __shared__ __align__(16) unsigned char smem_raw[64 * ZS_STRIDE * 4];
    __nv_bfloat16* As = (__nv_bfloat16*)smem_raw;
    __nv_bfloat16* Bs = (__nv_bfloat16*)(smem_raw + 10240);
    float* zs = (float*)smem_raw;

    int K, boundk, lda0;
    const __nv_bfloat16 *A0, *A1, *Wm;
    float* cst;
    __nv_bfloat16* hout;
    const int pout = pin ^ 1;

    if (layer == 0) {
        K = K1; boundk = DD; lda0 = DD;
        A0 = g_X + (size_t)t * BB * DD;
        A1 = g_h1[pin];
        Wm = g_W1; cst = g_c1; hout = g_h1[pout];
    } else {
        K = K2; boundk = HH; lda0 = HH;
        A0 = g_h1[pout];
        A1 = g_h2[pin];
        Wm = g_W2; cst = g_c2; hout = g_h2[pout];
    }

    const int n0 = blockIdx.x * 32;
    const int m0 = blockIdx.y * 64;
    const int tid = threadIdx.x;
    const int lane = tid & 31;
    const int wid = tid >> 5;
    const int wm = wid & 3;
    const int wn = wid >> 2;
    const int rowA = tid >> 2;
    const int quadA = tid & 3;

    float acc[8][4];
#pragma unroll
    for (int j = 0; j < 8; j++)
#pragma unroll
        for (int q = 0; q < 4; q++) acc[j][q] = 0.f;

    auto load_stage = [&](int kt, int s) {
        const int k0 = kt * 32;
        const __nv_bfloat16* gpA;
        if (k0 < boundk) gpA = A0 + (size_t)(m0 + rowA) * lda0 + k0 + quadA * 8;
        else             gpA = A1 + (size_t)(m0 + rowA) * HH + (k0 - boundk) + quadA * 8;
        uint32_t dstA = smem_u32(As + s * 64 * AS_STRIDE + rowA * AS_STRIDE + quadA * 8);
        asm volatile("cp.async.cg.shared.global [%0], [%1], 16;\n" :: "r"(dstA), "l"(gpA));
#pragma unroll
        for (int i = 0; i < 2; i++) {
            int c = tid + i * 256;
            int kk = c >> 4;
            int ncv = (c & 15) * 8;
            int g = ncv >> 5;
            int col = g * HH + n0 + (ncv & 31);
            const __nv_bfloat16* gpB = Wm + (size_t)(k0 + kk) * FOURH + col;
            uint32_t dstB = smem_u32(Bs + s * 32 * BS_STRIDE + kk * BS_STRIDE + ncv);
            asm volatile("cp.async.cg.shared.global [%0], [%1], 16;\n" :: "r"(dstB), "l"(gpB));
        }
    };

    load_stage(0, 0);
    asm volatile("cp.async.commit_group;\n" ::: "memory");

    const int nK = K >> 5;
    for (int kt = 0; kt < nK; ++kt) {
        const int s = kt & 1;
        if (kt + 1 < nK) load_stage(kt + 1, s ^ 1);
        asm volatile("cp.async.commit_group;\n" ::: "memory");
        asm volatile("cp.async.wait_group 1;\n" ::: "memory");
        __syncthreads();

#pragma unroll
        for (int ks = 0; ks < 2; ++ks) {
            uint32_t a0, a1, a2, a3;
            {
                int row = wm * 16 + (lane & 15);
                int colb = ks * 16 + (lane >> 4) * 8;
                uint32_t addr = smem_u32(As + s * 64 * AS_STRIDE + row * AS_STRIDE + colb);
                asm volatile("ldmatrix.sync.aligned.m8n8.x4.shared.b16 {%0,%1,%2,%3}, [%4];\n"
                             : "=r"(a0), "=r"(a1), "=r"(a2), "=r"(a3) : "r"(addr));
            }
#pragma unroll
            for (int j2 = 0; j2 < 4; j2++) {
                uint32_t b0, b1, b2, b3;
                int krow = ks * 16 + (lane & 7) + ((lane >> 3) & 1) * 8;
                int ncol = wn * 64 + j2 * 16 + (lane >> 4) * 8;
                uint32_t addr = smem_u32(Bs + s * 32 * BS_STRIDE + krow * BS_STRIDE + ncol);
                asm volatile("ldmatrix.sync.aligned.m8n8.x4.trans.shared.b16 {%0,%1,%2,%3}, [%4];\n"
                             : "=r"(b0), "=r"(b1), "=r"(b2), "=r"(b3) : "r"(addr));
                asm volatile("mma.sync.aligned.m16n8k16.row.col.f32.bf16.bf16.f32 "
                             "{%0,%1,%2,%3}, {%4,%5,%6,%7}, {%8,%9}, {%0,%1,%2,%3};\n"
                             : "+f"(acc[2 * j2][0]), "+f"(acc[2 * j2][1]),
                               "+f"(acc[2 * j2][2]), "+f"(acc[2 * j2][3])
                             : "r"(a0), "r"(a1), "r"(a2), "r"(a3), "r"(b0), "r"(b1));
                asm volatile("mma.sync.aligned.m16n8k16.row.col.f32.bf16.bf16.f32 "
                             "{%0,%1,%2,%3}, {%4,%5,%6,%7}, {%8,%9}, {%0,%1,%2,%3};\n"
                             : "+f"(acc[2 * j2 + 1][0]), "+f"(acc[2 * j2 + 1][1]),
                               "+f"(acc[2 * j2 + 1][2]), "+f"(acc[2 * j2 + 1][3])
                             : "r"(a0), "r"(a1), "r"(a2), "r"(a3), "r"(b2), "r"(b3));
            }
        }
        __syncthreads();
    }

#pragma unroll
    for (int j = 0; j < 8; j++) {
        int col = wn * 64 + j * 8 + (lane & 3) * 2;
        int r = wm * 16 + (lane >> 2);
        zs[r * ZS_STRIDE + col]           = acc[j][0];
        zs[r * ZS_STRIDE + col + 1]       = acc[j][1];
        zs[(r + 8) * ZS_STRIDE + col]     = acc[j][2];
        zs[(r + 8) * ZS_STRIDE + col + 1] = acc[j][3];
    }
    __syncthreads();

#pragma unroll
    for (int e = tid; e < 64 * 32; e += 256) {
        int r = e >> 5;
        int hc = e & 31;
        float zi = zs[r * ZS_STRIDE + hc]        + bias[0 * HH + n0 + hc];
        float zj = zs[r * ZS_STRIDE + 32 + hc]   + bias[1 * HH + n0 + hc];
        float zf = zs[r * ZS_STRIDE + 64 + hc]   + bias[2 * HH + n0 + hc];
        float zo = zs[r * ZS_STRIDE + 96 + hc]   + bias[3 * HH + n0 + hc];
        int gi = (m0 + r) * HH + n0 + hc;
        float c = cst[gi];
        float ncell = c * sigmoidf_(zf + 1.f) + sigmoidf_(zi) * tanhf(zj);
        float nh = tanhf(ncell) * sigmoidf_(zo);
        cst[gi] = ncell;
        hout[gi] = __float2bfloat16(nh);
    }
}

// ---------------- dense head + loss ----------------
__global__ void head_kernel(const float* __restrict__ Wd, const float* __restrict__ bd,
                            const float* __restrict__ labels) {
    const int b = blockIdx.x;
    const int lane = threadIdx.x & 31;
    const int w = threadIdx.x >> 5;
    const __nv_bfloat16* h = g_h2[0];  // T=336 even -> final h2 in slot 0
    __shared__ float warpsum[8];
    float total = 0.f;
    for (int l = w; l < 24; l += 8) {
        float s = 0.f;
        for (int k = lane; k < HH; k += 32)
            s += __bfloat162float(h[b * HH + k]) * Wd[k * 24 + l];
#pragma unroll
        for (int off = 16; off; off >>= 1) s += __shfl_xor_sync(0xffffffffu, s, off);
        if (lane == 0) {
            float pred = s + bd[l];
            float e = pred - labels[b * 24 + l];
            total += e * e;
        }
    }
    if (lane == 0) warpsum[w] = total;
    __syncthreads();
    if (threadIdx.x == 0) {
        float acc = 0.f;
#pragma unroll
        for (int i = 0; i < 8; i++) acc += warpsum[i];
        g_partial[b] = acc;
    }
}

__global__ void finish_kernel(float* __restrict__ out) {
    __shared__ float sh[256];
    sh[threadIdx.x] = g_partial[threadIdx.x];
    __syncthreads();
    for (int s = 128; s; s >>= 1) {
        if (threadIdx.x < s) sh[threadIdx.x] += sh[threadIdx.x + s];
        __syncthreads();
    }
    if (threadIdx.x == 0) out[0] = sh[0] / (float)(BB * 24);
}

// ---------------- launch ----------------
extern "C" void kernel_launch(void* const* d_in, const int* in_sizes, int n_in,
                              void* d_out, int out_size) {
    const float* features = (const float*)d_in[0];
    const float* labels   = (const float*)d_in[1];
    const float* W1       = (const float*)d_in[2];
    const float* b1       = (const float*)d_in[3];
    const float* W2       = (const float*)d_in[4];
    const float* b2       = (const float*)d_in[5];
    const float* Wd       = (const float*)d_in[6];
    const float* bd       = (const float*)d_in[7];
    float* out = (float*)d_out;

    // Dispatch on which binary got the real tcgen05 kernel (stub ~few regs).
    static int use_tc = -1;
    if (use_tc < 0) {
        cudaFuncAttributes attr{};
        cudaFuncGetAttributes(&attr, lstm_persist);
        use_tc = (attr.numRegs > 40) ? 1 : 0;
        if (use_tc) {
            cudaFuncSetAttribute(lstm_persist,
                                 cudaFuncAttributeMaxDynamicSharedMemorySize, SMEM_DYN);
        }
    }

    if (use_tc) {
        conv_w_t<<<dim3(K1 / 32, 32, 4), dim3(32, 8)>>>(W1, 0, K1);
        conv_w_t<<<dim3(K2 / 32, 32, 4), dim3(32, 8)>>>(W2, 1, K2);
    } else {
        conv_w_kernel<<<592, 256>>>(W1, 0, K1 * FOURH);
        conv_w_kernel<<<592, 256>>>(W2, 1, K2 * FOURH);
    }
    conv_x_kernel<<<592, 256>>>(features);
    init_state_kernel<<<512, 256>>>();

    if (use_tc) {
        lstm_persist<<<NCTA, 256, SMEM_DYN>>>(b1, b2);
    } else {
        dim3 grid(32, 4);
        for (int t = 0; t < TT; t++) {
            int p = t & 1;
            lstm_step_fb<<<grid, 256>>>(0, t, p, b1);
            lstm_step_fb<<<grid, 256>>>(1, t, p, b2);
        }
    }

    head_kernel<<<BB, 256>>>(Wd, bd, labels);
    finish_kernel<<<1, 256>>>(out);
}

// round 6
// speedup vs baseline: 2.7219x; 1.9304x over previous
#include <cuda_runtime.h>
#include <cuda.h>
#include <cuda_bf16.h>
#include <cstdint>

#define BB 256
#define TT 336
#define DD 128
#define HH 1024
#define K1 1152
#define K2 2048
#define FOURH 4096

#define STAGES 6
#define STAGE_BYTES 32768         // A tile 16KB + B tile 16KB
#define SMEM_DYN (STAGES * STAGE_BYTES + 1024)
#define NCTA 64
#define CLUSTER 4

// ---- arch-feature gate ----
#if defined(__CUDA_ARCH__) && \
    (defined(__CUDA_ARCH_FEAT_SM103_ALL) || defined(__CUDA_ARCH_FEAT_SM100_ALL) || \
     (defined(__CUDA_ARCH_SPECIFIC__) && (__CUDA_ARCH_SPECIFIC__ >= 1000)) || \
     (defined(__CUDA_ARCH_FAMILY_SPECIFIC__) && (__CUDA_ARCH_FAMILY_SPECIFIC__ >= 1000)))
#define HAS_TCGEN05 1
#else
#define HAS_TCGEN05 0
#endif

// ---------------- device-global scratch ----------------
__device__ __nv_bfloat16 g_W1[K1 * FOURH];   // tc: [n_global][K] K-major; fb: [k][4096]
__device__ __nv_bfloat16 g_W2[K2 * FOURH];
__device__ __nv_bfloat16 g_X[TT * BB * DD];  // [t][b][d]
__device__ __nv_bfloat16 g_h1[2][BB * HH];
__device__ __nv_bfloat16 g_h2[2][BB * HH];
__device__ float g_c1[BB * HH];
__device__ float g_c2[BB * HH];
__device__ float g_partial[BB];
__device__ unsigned g_bar_ctr;

// ---------------- helpers ----------------
__device__ __forceinline__ uint32_t smem_u32(const void* p) {
    return (uint32_t)__cvta_generic_to_shared(p);
}
__device__ __forceinline__ float fast_tanh(float x) {
    float y;
    asm("tanh.approx.f32 %0, %1;" : "=f"(y) : "f"(x));
    return y;
}
__device__ __forceinline__ float fast_sigmoid(float x) {
    return 0.5f * fast_tanh(0.5f * x) + 0.5f;
}
__device__ __forceinline__ float sigmoidf_(float x) { return 1.f / (1.f + __expf(-x)); }

// ---------------- conversion / init kernels ----------------
__global__ void conv_w_t(const float* __restrict__ src, int which, int K) {
    __shared__ float tile[32][33];
    const int kb = blockIdx.x * 32, nt = blockIdx.y, g = blockIdx.z;
    const int tx = threadIdx.x, ty0 = threadIdx.y;
#pragma unroll
    for (int i = 0; i < 4; i++) {
        int ty = ty0 + i * 8;
        tile[ty][tx] = src[(size_t)(kb + ty) * FOURH + g * HH + nt * 32 + tx];
    }
    __syncthreads();
    __nv_bfloat16* dst = (which == 0) ? g_W1 : g_W2;
#pragma unroll
    for (int i = 0; i < 4; i++) {
        int ty = ty0 + i * 8;
        dst[(size_t)(nt * 128 + g * 32 + ty) * K + kb + tx] = __float2bfloat16(tile[tx][ty]);
    }
}

__global__ void conv_w_kernel(const float* __restrict__ src, int which, int n) {
    for (int i = blockIdx.x * blockDim.x + threadIdx.x; i < n; i += gridDim.x * blockDim.x) {
        __nv_bfloat16 v = __float2bfloat16(src[i]);
        if (which == 0) g_W1[i] = v;
        else            g_W2[i] = v;
    }
}

__global__ void conv_x_kernel(const float* __restrict__ f) {
    int n = BB * TT * DD;
    for (int i = blockIdx.x * blockDim.x + threadIdx.x; i < n; i += gridDim.x * blockDim.x) {
        int b = i / (TT * DD);
        int r = i % (TT * DD);
        int t = r / DD;
        int d = r % DD;
        g_X[(size_t)t * BB * DD + b * DD + d] = __float2bfloat16(f[i]);
    }
}

__global__ void init_state_kernel() {
    int n = BB * HH;
    __nv_bfloat16 z = __float2bfloat16(0.f);
    if (blockIdx.x == 0 && threadIdx.x == 0) g_bar_ctr = 0;
    for (int i = blockIdx.x * blockDim.x + threadIdx.x; i < n; i += gridDim.x * blockDim.x) {
        g_c1[i] = 0.f;
        g_c2[i] = 0.f;
        g_h1[0][i] = z;
        g_h2[0][i] = z;
    }
}

// ============================================================================
// tcgen05 + TMA PTX helpers ('a'-variant targets only)
// ============================================================================
#if HAS_TCGEN05

__device__ __forceinline__ uint32_t elect_one_pred() {
    uint32_t pred;
    asm volatile(
        "{\n\t.reg .pred p;\n\t"
        "elect.sync _|p, 0xFFFFFFFF;\n\t"
        "selp.b32 %0, 1, 0, p;\n\t}"
        : "=r"(pred));
    return pred;
}

#define MBARRIER_INIT(mbar, count) \
    asm volatile("mbarrier.init.shared.b64 [%0], %1;" :: "r"((uint32_t)(mbar)), "r"((uint32_t)(count)) : "memory")

#define MBARRIER_EXPECT_TX(mbar, bytes) \
    asm volatile("mbarrier.arrive.expect_tx.shared.b64 _, [%0], %1;" \
                 :: "r"((uint32_t)(mbar)), "r"((uint32_t)(bytes)) : "memory")

#define MBARRIER_WAIT_PARITY(mbar_addr, phase_parity) do {                          \
    uint32_t _mbar = (uint32_t)(mbar_addr);                                         \
    uint32_t _parity = (uint32_t)(phase_parity);                                    \
    uint32_t _done;                                                                 \
    asm volatile(                                                                   \
        "{\n\t.reg .pred p;\n\t"                                                    \
        "mbarrier.try_wait.parity.acquire.cta.shared::cta.b64 p, [%1], %2;\n\t"     \
        "selp.b32 %0, 1, 0, p;\n\t}"                                                \
        : "=r"(_done) : "r"(_mbar), "r"(_parity) : "memory");                       \
    if (!_done) {                                                                   \
        asm volatile(                                                               \
            "{\n\t.reg .pred P1;\n\t"                                               \
            "WAIT_LOOP_%=:\n\t"                                                     \
            "mbarrier.try_wait.parity.acquire.cta.shared::cta.b64 P1, [%0], %1, 0x989680;\n\t" \
            "@P1 bra.uni WAIT_DONE_%=;\n\t"                                         \
            "bra.uni WAIT_LOOP_%=;\n\t"                                             \
            "WAIT_DONE_%=:\n\t}"                                                    \
            :: "r"(_mbar), "r"(_parity) : "memory");                                \
    }                                                                               \
} while (0)

#define TMA_LOAD_3D_MULTICAST(smem_addr, tensor_map, cx, cy, cz, mbar, cta_mask) \
    asm volatile( \
        "cp.async.bulk.tensor.3d.shared::cluster.global.tile.mbarrier::complete_tx::bytes.multicast::cluster " \
        "[%0], [%1, {%2, %3, %4}], [%5], %6;" \
        :: "r"((uint32_t)(smem_addr)), "l"(tensor_map), \
           "r"((int32_t)(cx)), "r"((int32_t)(cy)), "r"((int32_t)(cz)), \
           "r"((uint32_t)(mbar)), "h"((uint16_t)(cta_mask)) \
        : "memory")

#define CLUSTER_SYNC() do { \
    asm volatile("barrier.cluster.arrive.aligned;" ::: "memory"); \
    asm volatile("barrier.cluster.wait.aligned;" ::: "memory"); \
} while (0)

#define TCGEN05_ALLOC(smem_result_addr, nCols) \
    asm volatile("tcgen05.alloc.cta_group::1.sync.aligned.shared::cta.b32 [%0], %1;" \
                 :: "r"((uint32_t)(smem_result_addr)), "r"((uint32_t)(nCols)) : "memory")
#define TCGEN05_DEALLOC(tmem_addr, nCols) \
    asm volatile("tcgen05.dealloc.cta_group::1.sync.aligned.b32 %0, %1;" \
                 :: "r"(tmem_addr), "r"((uint32_t)(nCols)))
#define TCGEN05_RELINQUISH() \
    asm volatile("tcgen05.relinquish_alloc_permit.cta_group::1.sync.aligned;")
#define TCGEN05_COMMIT(mbar_addr) \
    asm volatile("tcgen05.commit.cta_group::1.mbarrier::arrive::one.shared::cluster.b64 [%0];" \
                 :: "r"((uint32_t)(mbar_addr)) : "memory")
#define TCGEN05_COMMIT_MULTICAST(mbar_addr, cta_mask) \
    asm volatile("tcgen05.commit.cta_group::1.mbarrier::arrive::one.shared::cluster.multicast::cluster.b64 [%0], %1;" \
                 :: "r"((uint32_t)(mbar_addr)), "h"((uint16_t)(cta_mask)) : "memory")
#define TCGEN05_WAIT_LD()  asm volatile("tcgen05.wait::ld.sync.aligned;" ::: "memory")
#define TCGEN05_FENCE_AFTER()  asm volatile("tcgen05.fence::after_thread_sync;" ::: "memory")
#define TCGEN05_FENCE_BEFORE() asm volatile("tcgen05.fence::before_thread_sync;" ::: "memory")

#define TCGEN05_LD_X32(r, tmem_addr) \
    asm volatile( \
        "tcgen05.ld.sync.aligned.32x32b.x32.b32 " \
        "{%0, %1, %2, %3, %4, %5, %6, %7, " \
        " %8, %9, %10, %11, %12, %13, %14, %15, " \
        " %16, %17, %18, %19, %20, %21, %22, %23, " \
        " %24, %25, %26, %27, %28, %29, %30, %31}, [%32];" \
        : "=r"((r)[0]),  "=r"((r)[1]),  "=r"((r)[2]),  "=r"((r)[3]), \
          "=r"((r)[4]),  "=r"((r)[5]),  "=r"((r)[6]),  "=r"((r)[7]), \
          "=r"((r)[8]),  "=r"((r)[9]),  "=r"((r)[10]), "=r"((r)[11]), \
          "=r"((r)[12]), "=r"((r)[13]), "=r"((r)[14]), "=r"((r)[15]), \
          "=r"((r)[16]), "=r"((r)[17]), "=r"((r)[18]), "=r"((r)[19]), \
          "=r"((r)[20]), "=r"((r)[21]), "=r"((r)[22]), "=r"((r)[23]), \
          "=r"((r)[24]), "=r"((r)[25]), "=r"((r)[26]), "=r"((r)[27]), \
          "=r"((r)[28]), "=r"((r)[29]), "=r"((r)[30]), "=r"((r)[31]) \
        : "r"(tmem_addr))

__device__ __forceinline__ uint64_t sdesc_sw128(uint32_t addr) {
    return (2ULL << 61) | (1ULL << 46) | (64ULL << 32) | (1ULL << 16) |
           (uint64_t)((addr >> 4) & 0x3FFF);
}

// idesc kind::f16: dtype=F32, atype=btype=BF16, N=128, M=128
#define MMA_IDESC ((1u << 4) | (1u << 7) | (1u << 10) | ((128u / 8) << 17) | ((128u / 16) << 24))

__device__ __forceinline__ void mma_f16_ss(uint32_t d, uint64_t ad, uint64_t bd,
                                           uint32_t idesc, unsigned en) {
    asm volatile(
        "{\n\t.reg .pred p;\n\t"
        "setp.ne.u32 p, %5, 0;\n\t"
        "tcgen05.mma.cta_group::1.kind::f16 [%0], %1, %2, %3, {%4, %4, %4, %4}, p;\n\t}"
        :: "r"(d), "l"(ad), "l"(bd), "r"(idesc), "r"(0u), "r"(en) : "memory");
}

#endif // HAS_TCGEN05

// ============================================================================
// PERSISTENT tcgen05 kernel with TMA multicast. Cluster (4,1,1):
//   rank r: nt_local = r>>1, m = r&1. A shared by same-m pairs {r, r^2},
//   B shared by same-nt pairs {r, r^1}. Cooperative-sliced multicast:
//   each CTA loads one 8KB slice of A and one of B per 64-K chunk.
// Warp 0 = MMA issuer, warp 1 = TMA producer, all warps epilogue.
// ============================================================================
__global__ __launch_bounds__(256, 1)
void lstm_persist(const __grid_constant__ CUtensorMap tmx,
                  const __grid_constant__ CUtensorMap tmh1,
                  const __grid_constant__ CUtensorMap tmh2,
                  const __grid_constant__ CUtensorMap tmw1,
                  const __grid_constant__ CUtensorMap tmw2,
                  const float* __restrict__ b1, const float* __restrict__ b2) {
#if HAS_TCGEN05
    extern __shared__ __align__(1024) unsigned char sm[];
    const uint32_t smem_base = smem_u32(sm);
    const int tid = threadIdx.x;
    const int wid = tid >> 5;
    const int lane = tid & 31;

    const int r = (int)(blockIdx.x & 3);           // cluster rank
    const int nt = (int)((blockIdx.x >> 2) * 2 + (r >> 1));
    const int m0 = (r & 1) * 128;
    const int ar = r >> 1;                          // A slice index within pair
    const int bm = r & 1;                           // B slice index within pair
    const uint16_t amask = (uint16_t)((1u << r) | (1u << (r ^ 2)));
    const uint16_t bmask = (uint16_t)((1u << r) | (1u << (r ^ 1)));
    const uint16_t emask = (uint16_t)((1u << r) | (1u << (r ^ 1)) | (1u << (r ^ 2)));

    const uint32_t ctrl = smem_base + STAGES * STAGE_BYTES;   // tmem ptr (16B)
    const uint32_t mb_full = ctrl + 16;                        // [STAGES] x 8B
    const uint32_t mb_empty = mb_full + 8 * STAGES;            // [STAGES] x 8B
    const uint32_t mb_done = mb_empty + 8 * STAGES;

    if (wid == 0) TCGEN05_ALLOC(ctrl, 128);
    if (tid == 0) {
#pragma unroll
        for (int s = 0; s < STAGES; s++) {
            MBARRIER_INIT(mb_full + 8 * s, 1);     // expect_tx arrival
            MBARRIER_INIT(mb_empty + 8 * s, 3);    // commits from self, r^1, r^2
        }
        MBARRIER_INIT(mb_done, 1);
    }
    __syncthreads();
    CLUSTER_SYNC();   // all cluster mbarriers initialized before any multicast
    uint32_t tmem_base;
    asm volatile("ld.shared.b32 %0, [%1];" : "=r"(tmem_base) : "r"(ctrl));

    int done_par = 0;
    unsigned gj = 0;       // running global chunk counter
    unsigned bar_n = 0;

    for (int t = 0; t < TT; t++) {
        const int pin = t & 1;
        const int pout = pin ^ 1;
#pragma unroll 1
        for (int layer = 0; layer < 2; layer++) {
            const int nc = (layer == 0) ? (K1 / 64) : (K2 / 64);
            float* cst = (layer == 0) ? g_c1 : g_c2;
            __nv_bfloat16* hout = (layer == 0) ? g_h1[pout] : g_h2[pout];
            const float* bias = (layer == 0) ? b1 : b2;

            if (wid == 1) {
                // ---------------- producer: TMA issuer ----------------
                for (int c = 0; c < nc; ++c) {
                    const unsigned G = gj + (unsigned)c;
                    const int s = (int)(G % STAGES);
                    const unsigned n = G / STAGES;
                    if (n > 0) MBARRIER_WAIT_PARITY(mb_empty + 8 * s, (int)((n - 1) & 1));
                    if (elect_one_pred()) {
                        const uint32_t sbase = smem_base + s * STAGE_BYTES;
                        const uint32_t fb = mb_full + 8 * s;
                        MBARRIER_EXPECT_TX(fb, 32768);
                        const int k0 = c * 64;
                        // A slice (multicast to same-m pair)
                        const CUtensorMap* tA;
                        int cxA, czA;
                        if (layer == 0) {
                            if (k0 < DD) { tA = &tmx;  cxA = k0;       czA = t; }
                            else         { tA = &tmh1; cxA = k0 - DD;  czA = pin; }
                        } else {
                            if (k0 < HH) { tA = &tmh1; cxA = k0;       czA = pout; }
                            else         { tA = &tmh2; cxA = k0 - HH;  czA = pin; }
                        }
                        TMA_LOAD_3D_MULTICAST(sbase + ar * 8192, tA,
                                              cxA, m0 + ar * 64, czA, fb, amask);
                        // B slice (multicast to same-nt pair)
                        const CUtensorMap* tB = (layer == 0) ? &tmw1 : &tmw2;
                        TMA_LOAD_3D_MULTICAST(sbase + 16384 + bm * 8192, tB,
                                              k0, nt * 128 + bm * 64, 0, fb, bmask);
                    }
                }
            } else if (wid == 0) {
                // ---------------- consumer: MMA issuer ----------------
                for (int c = 0; c < nc; ++c) {
                    const unsigned G = gj + (unsigned)c;
                    const int s = (int)(G % STAGES);
                    const unsigned n = G / STAGES;
                    MBARRIER_WAIT_PARITY(mb_full + 8 * s, (int)(n & 1));
                    if (elect_one_pred()) {
                        const uint64_t ad = sdesc_sw128(smem_base + s * STAGE_BYTES);
                        const uint64_t bd = sdesc_sw128(smem_base + s * STAGE_BYTES + 16384);
#pragma unroll
                        for (int kk = 0; kk < 4; kk++)
                            mma_f16_ss(tmem_base, ad + kk * 2, bd + kk * 2, MMA_IDESC,
                                       (unsigned)((c | kk) != 0));
                        TCGEN05_COMMIT_MULTICAST(mb_empty + 8 * s, emask);
                    }
                }
                if (elect_one_pred()) TCGEN05_COMMIT(mb_done);
            }

            // ---- all warps: wait GEMM completion ----
            MBARRIER_WAIT_PARITY(mb_done, done_par);
            done_par ^= 1;
            TCGEN05_FENCE_AFTER();

            // ---- epilogue: LDTM -> smem -> fused LSTM cell ----
            {
                uint32_t regs[64];
                const uint32_t cb = (uint32_t)(wid >> 2) * 64;
                TCGEN05_LD_X32(regs, tmem_base + cb);
                TCGEN05_LD_X32(regs + 32, tmem_base + cb + 32);
                TCGEN05_WAIT_LD();
                TCGEN05_FENCE_BEFORE();

                float* zs = (float*)sm;   // [128][133] overlays drained stage smem
                const int row = (wid & 3) * 32 + lane;
#pragma unroll
                for (int c2 = 0; c2 < 64; c2++)
                    zs[row * 133 + cb + c2] = __uint_as_float(regs[c2]);
                __syncthreads();

                const int hb = nt * 32;
                for (int e = tid; e < 128 * 32; e += 256) {
                    const int rr = e >> 5;
                    const int hc = e & 31;
                    float zi = zs[rr * 133 + hc]      + bias[hb + hc];
                    float zj = zs[rr * 133 + 32 + hc] + bias[HH + hb + hc];
                    float zf = zs[rr * 133 + 64 + hc] + bias[2 * HH + hb + hc];
                    float zo = zs[rr * 133 + 96 + hc] + bias[3 * HH + hb + hc];
                    const int gi = (m0 + rr) * HH + hb + hc;
                    float cc = cst[gi];
                    float ncell = cc * fast_sigmoid(zf + 1.f) +
                                  fast_sigmoid(zi) * fast_tanh(zj);
                    hout[gi] = __float2bfloat16(fast_tanh(ncell) * fast_sigmoid(zo));
                    cst[gi] = ncell;
                }
            }

            gj += (unsigned)nc;

            // ---- grid barrier: h visible chip-wide before next GEMM ----
            bar_n++;
            __syncthreads();
            if (tid == 0) {
                __threadfence();
                atomicAdd(&g_bar_ctr, 1u);
                const unsigned tgt = bar_n * NCTA;
                while (*(volatile unsigned*)&g_bar_ctr < tgt) { }
            }
            __syncthreads();
        }
    }

    CLUSTER_SYNC();
    if (wid == 0) {
        TCGEN05_RELINQUISH();
        TCGEN05_DEALLOC(tmem_base, 128);
    }
#endif // HAS_TCGEN05
}

// ============================================================================
// Fallback: mma.sync (HMMA) fused step kernel (round-1 proven path).
// ============================================================================
#define AS_STRIDE 40
#define BS_STRIDE 136
#define ZS_STRIDE 132

__global__ __launch_bounds__(256, 1)
void lstm_step_fb(int layer, int t, int pin, const float* __restrict__ bias) {
    __shared__ __align__(16) unsigned char smem_raw[64 * ZS_STRIDE * 4];
    __nv_bfloat16* As = (__nv_bfloat16*)smem_raw;
    __nv_bfloat16* Bs = (__nv_bfloat16*)(smem_raw + 10240);
    float* zs = (float*)smem_raw;

    int K, boundk, lda0;
    const __nv_bfloat16 *A0, *A1, *Wm;
    float* cst;
    __nv_bfloat16* hout;
    const int pout = pin ^ 1;

    if (layer == 0) {
        K = K1; boundk = DD; lda0 = DD;
        A0 = g_X + (size_t)t * BB * DD;
        A1 = g_h1[pin];
        Wm = g_W1; cst = g_c1; hout = g_h1[pout];
    } else {
        K = K2; boundk = HH; lda0 = HH;
        A0 = g_h1[pout];
        A1 = g_h2[pin];
        Wm = g_W2; cst = g_c2; hout = g_h2[pout];
    }

    const int n0 = blockIdx.x * 32;
    const int m0 = blockIdx.y * 64;
    const int tid = threadIdx.x;
    const int lane = tid & 31;
    const int wid = tid >> 5;
    const int wm = wid & 3;
    const int wn = wid >> 2;
    const int rowA = tid >> 2;
    const int quadA = tid & 3;

    float acc[8][4];
#pragma unroll
    for (int j = 0; j < 8; j++)
#pragma unroll
        for (int q = 0; q < 4; q++) acc[j][q] = 0.f;

    auto load_stage = [&](int kt, int s) {
        const int k0 = kt * 32;
        const __nv_bfloat16* gpA;
        if (k0 < boundk) gpA = A0 + (size_t)(m0 + rowA) * lda0 + k0 + quadA * 8;
        else             gpA = A1 + (size_t)(m0 + rowA) * HH + (k0 - boundk) + quadA * 8;
        uint32_t dstA = smem_u32(As + s * 64 * AS_STRIDE + rowA * AS_STRIDE + quadA * 8);
        asm volatile("cp.async.cg.shared.global [%0], [%1], 16;\n" :: "r"(dstA), "l"(gpA));
#pragma unroll
        for (int i = 0; i < 2; i++) {
            int c = tid + i * 256;
            int kk = c >> 4;
            int ncv = (c & 15) * 8;
            int g = ncv >> 5;
            int col = g * HH + n0 + (ncv & 31);
            const __nv_bfloat16* gpB = Wm + (size_t)(k0 + kk) * FOURH + col;
            uint32_t dstB = smem_u32(Bs + s * 32 * BS_STRIDE + kk * BS_STRIDE + ncv);
            asm volatile("cp.async.cg.shared.global [%0], [%1], 16;\n" :: "r"(dstB), "l"(gpB));
        }
    };

    load_stage(0, 0);
    asm volatile("cp.async.commit_group;\n" ::: "memory");

    const int nK = K >> 5;
    for (int kt = 0; kt < nK; ++kt) {
        const int s = kt & 1;
        if (kt + 1 < nK) load_stage(kt + 1, s ^ 1);
        asm volatile("cp.async.commit_group;\n" ::: "memory");
        asm volatile("cp.async.wait_group 1;\n" ::: "memory");
        __syncthreads();

#pragma unroll
        for (int ks = 0; ks < 2; ++ks) {
            uint32_t a0, a1, a2, a3;
            {
                int row = wm * 16 + (lane & 15);
                int colb = ks * 16 + (lane >> 4) * 8;
                uint32_t addr = smem_u32(As + s * 64 * AS_STRIDE + row * AS_STRIDE + colb);
                asm volatile("ldmatrix.sync.aligned.m8n8.x4.shared.b16 {%0,%1,%2,%3}, [%4];\n"
                             : "=r"(a0), "=r"(a1), "=r"(a2), "=r"(a3) : "r"(addr));
            }
#pragma unroll
            for (int j2 = 0; j2 < 4; j2++) {
                uint32_t b0, b1, b2, b3;
                int krow = ks * 16 + (lane & 7) + ((lane >> 3) & 1) * 8;
                int ncol = wn * 64 + j2 * 16 + (lane >> 4) * 8;
                uint32_t addr = smem_u32(Bs + s * 32 * BS_STRIDE + krow * BS_STRIDE + ncol);
                asm volatile("ldmatrix.sync.aligned.m8n8.x4.trans.shared.b16 {%0,%1,%2,%3}, [%4];\n"
                             : "=r"(b0), "=r"(b1), "=r"(b2), "=r"(b3) : "r"(addr));
                asm volatile("mma.sync.aligned.m16n8k16.row.col.f32.bf16.bf16.f32 "
                             "{%0,%1,%2,%3}, {%4,%5,%6,%7}, {%8,%9}, {%0,%1,%2,%3};\n"
                             : "+f"(acc[2 * j2][0]), "+f"(acc[2 * j2][1]),
                               "+f"(acc[2 * j2][2]), "+f"(acc[2 * j2][3])
                             : "r"(a0), "r"(a1), "r"(a2), "r"(a3), "r"(b0), "r"(b1));
                asm volatile("mma.sync.aligned.m16n8k16.row.col.f32.bf16.bf16.f32 "
                             "{%0,%1,%2,%3}, {%4,%5,%6,%7}, {%8,%9}, {%0,%1,%2,%3};\n"
                             : "+f"(acc[2 * j2 + 1][0]), "+f"(acc[2 * j2 + 1][1]),
                               "+f"(acc[2 * j2 + 1][2]), "+f"(acc[2 * j2 + 1][3])
                             : "r"(a0), "r"(a1), "r"(a2), "r"(a3), "r"(b2), "r"(b3));
            }
        }
        __syncthreads();
    }

#pragma unroll
    for (int j = 0; j < 8; j++) {
        int col = wn * 64 + j * 8 + (lane & 3) * 2;
        int rr = wm * 16 + (lane >> 2);
        zs[rr * ZS_STRIDE + col]           = acc[j][0];
        zs[rr * ZS_STRIDE + col + 1]       = acc[j][1];
        zs[(rr + 8) * ZS_STRIDE + col]     = acc[j][2];
        zs[(rr + 8) * ZS_STRIDE + col + 1] = acc[j][3];
    }
    __syncthreads();

#pragma unroll
    for (int e = tid; e < 64 * 32; e += 256) {
        int rr = e >> 5;
        int hc = e & 31;
        float zi = zs[rr * ZS_STRIDE + hc]        + bias[0 * HH + n0 + hc];
        float zj = zs[rr * ZS_STRIDE + 32 + hc]   + bias[1 * HH + n0 + hc];
        float zf = zs[rr * ZS_STRIDE + 64 + hc]   + bias[2 * HH + n0 + hc];
        float zo = zs[rr * ZS_STRIDE + 96 + hc]   + bias[3 * HH + n0 + hc];
        int gi = (m0 + rr) * HH + n0 + hc;
        float c = cst[gi];
        float ncell = c * sigmoidf_(zf + 1.f) + sigmoidf_(zi) * tanhf(zj);
        float nh = tanhf(ncell) * sigmoidf_(zo);
        cst[gi] = ncell;
        hout[gi] = __float2bfloat16(nh);
    }
}

// ---------------- dense head + loss ----------------
__global__ void head_kernel(const float* __restrict__ Wd, const float* __restrict__ bd,
                            const float* __restrict__ labels) {
    const int b = blockIdx.x;
    const int lane = threadIdx.x & 31;
    const int w = threadIdx.x >> 5;
    const __nv_bfloat16* h = g_h2[0];  // T=336 even -> final h2 in slot 0
    __shared__ float warpsum[8];
    float total = 0.f;
    for (int l = w; l < 24; l += 8) {
        float s = 0.f;
        for (int k = lane; k < HH; k += 32)
            s += __bfloat162float(h[b * HH + k]) * Wd[k * 24 + l];
#pragma unroll
        for (int off = 16; off; off >>= 1) s += __shfl_xor_sync(0xffffffffu, s, off);
        if (lane == 0) {
            float pred = s + bd[l];
            float e = pred - labels[b * 24 + l];
            total += e * e;
        }
    }
    if (lane == 0) warpsum[w] = total;
    __syncthreads();
    if (threadIdx.x == 0) {
        float acc = 0.f;
#pragma unroll
        for (int i = 0; i < 8; i++) acc += warpsum[i];
        g_partial[b] = acc;
    }
}

__global__ void finish_kernel(float* __restrict__ out) {
    __shared__ float sh[256];
    sh[threadIdx.x] = g_partial[threadIdx.x];
    __syncthreads();
    for (int s = 128; s; s >>= 1) {
        if (threadIdx.x < s) sh[threadIdx.x] += sh[threadIdx.x + s];
        __syncthreads();
    }
    if (threadIdx.x == 0) out[0] = sh[0] / (float)(BB * 24);
}

// ---------------- host: tensormap encoding ----------------
typedef CUresult (*encode_fn_t)(
    CUtensorMap*, CUtensorMapDataType, cuuint32_t, void*,
    const cuuint64_t*, const cuuint64_t*, const cuuint32_t*, const cuuint32_t*,
    CUtensorMapInterleave, CUtensorMapSwizzle, CUtensorMapL2promotion,
    CUtensorMapFloatOOBfill);

static bool encode_map(encode_fn_t enc, CUtensorMap* tm, void* base,
                       uint64_t d0, uint64_t d1, uint64_t d2,
                       uint64_t s1_bytes, uint64_t s2_bytes) {
    cuuint64_t dims[3] = {d0, d1, d2};
    cuuint64_t strides[2] = {s1_bytes, s2_bytes};
    cuuint32_t box[3] = {64, 64, 1};
    cuuint32_t es[3] = {1, 1, 1};
    CUresult res = enc(tm, CU_TENSOR_MAP_DATA_TYPE_BFLOAT16, 3, base,
                       dims, strides, box, es,
                       CU_TENSOR_MAP_INTERLEAVE_NONE, CU_TENSOR_MAP_SWIZZLE_128B,
                       CU_TENSOR_MAP_L2_PROMOTION_L2_128B,
                       CU_TENSOR_MAP_FLOAT_OOB_FILL_NONE);
    return res == CUDA_SUCCESS;
}

// ---------------- launch ----------------
extern "C" void kernel_launch(void* const* d_in, const int* in_sizes, int n_in,
                              void* d_out, int out_size) {
    const float* features = (const float*)d_in[0];
    const float* labels   = (const float*)d_in[1];
    const float* W1       = (const float*)d_in[2];
    const float* b1       = (const float*)d_in[3];
    const float* W2       = (const float*)d_in[4];
    const float* b2       = (const float*)d_in[5];
    const float* Wd       = (const float*)d_in[6];
    const float* bd       = (const float*)d_in[7];
    float* out = (float*)d_out;

    static CUtensorMap tmx, tmh1, tmh2, tmw1, tmw2;
    static int use_tc = -1;
    if (use_tc < 0) {
        use_tc = 0;
        cudaFuncAttributes attr{};
        cudaFuncGetAttributes(&attr, lstm_persist);
        if (attr.numRegs > 40) {
            void* fp = nullptr;
            cudaDriverEntryPointQueryResult qr = cudaDriverEntryPointSuccess;
            cudaGetDriverEntryPointByVersion("cuTensorMapEncodeTiled", &fp, 12000,
                                             cudaEnableDefault, &qr);
            void *px = nullptr, *ph1 = nullptr, *ph2 = nullptr, *pw1 = nullptr, *pw2 = nullptr;
            cudaGetSymbolAddress(&px, g_X);
            cudaGetSymbolAddress(&ph1, g_h1);
            cudaGetSymbolAddress(&ph2, g_h2);
            cudaGetSymbolAddress(&pw1, g_W1);
            cudaGetSymbolAddress(&pw2, g_W2);
            if (fp && px && ph1 && ph2 && pw1 && pw2) {
                encode_fn_t enc = (encode_fn_t)fp;
                bool ok = true;
                ok &= encode_map(enc, &tmx,  px,  DD,  BB, TT, (uint64_t)DD * 2, (uint64_t)BB * DD * 2);
                ok &= encode_map(enc, &tmh1, ph1, HH,  BB, 2,  (uint64_t)HH * 2, (uint64_t)BB * HH * 2);
                ok &= encode_map(enc, &tmh2, ph2, HH,  BB, 2,  (uint64_t)HH * 2, (uint64_t)BB * HH * 2);
                ok &= encode_map(enc, &tmw1, pw1, K1, FOURH, 1, (uint64_t)K1 * 2, (uint64_t)K1 * FOURH * 2);
                ok &= encode_map(enc, &tmw2, pw2, K2, FOURH, 1, (uint64_t)K2 * 2, (uint64_t)K2 * FOURH * 2);
                if (ok) {
                    use_tc = 1;
                    cudaFuncSetAttribute(lstm_persist,
                                         cudaFuncAttributeMaxDynamicSharedMemorySize, SMEM_DYN);
                }
            }
        }
    }

    if (use_tc) {
        conv_w_t<<<dim3(K1 / 32, 32, 4), dim3(32, 8)>>>(W1, 0, K1);
        conv_w_t<<<dim3(K2 / 32, 32, 4), dim3(32, 8)>>>(W2, 1, K2);
    } else {
        conv_w_kernel<<<592, 256>>>(W1, 0, K1 * FOURH);
        conv_w_kernel<<<592, 256>>>(W2, 1, K2 * FOURH);
    }
    conv_x_kernel<<<592, 256>>>(features);
    init_state_kernel<<<512, 256>>>();

    if (use_tc) {
        cudaLaunchConfig_t cfg = {};
        cfg.gridDim = dim3(NCTA, 1, 1);
        cfg.blockDim = dim3(256, 1, 1);
        cfg.dynamicSmemBytes = SMEM_DYN;
        cudaLaunchAttribute at[1];
        at[0].id = cudaLaunchAttributeClusterDimension;
        at[0].val.clusterDim.x = CLUSTER;
        at[0].val.clusterDim.y = 1;
        at[0].val.clusterDim.z = 1;
        cfg.attrs = at;
        cfg.numAttrs = 1;
        cudaLaunchKernelEx(&cfg, lstm_persist, tmx, tmh1, tmh2, tmw1, tmw2, b1, b2);
    } else {
        dim3 grid(32, 4);
        for (int t = 0; t < TT; t++) {
            int p = t & 1;
            lstm_step_fb<<<grid, 256>>>(0, t, p, b1);
            lstm_step_fb<<<grid, 256>>>(1, t, p, b2);
        }
    }

    head_kernel<<<BB, 256>>>(Wd, bd, labels);
    finish_kernel<<<1, 256>>>(out);
}

// round 8
// speedup vs baseline: 2.7474x; 1.0094x over previous
#include <cuda_runtime.h>
#include <cuda.h>
#include <cuda_bf16.h>
#include <cstdint>

#define BB 256
#define TT 336
#define DD 128
#define HH 1024
#define K1 1152
#define K2 2048
#define FOURH 4096

// ---- arch-feature gate ----
#if defined(__CUDA_ARCH__) && \
    (defined(__CUDA_ARCH_FEAT_SM103_ALL) || defined(__CUDA_ARCH_FEAT_SM100_ALL) || \
     (defined(__CUDA_ARCH_SPECIFIC__) && (__CUDA_ARCH_SPECIFIC__ >= 1000)) || \
     (defined(__CUDA_ARCH_FAMILY_SPECIFIC__) && (__CUDA_ARCH_FAMILY_SPECIFIC__ >= 1000)))
#define HAS_TCGEN05 1
#else
#define HAS_TCGEN05 0
#endif

// ---------------- device-global scratch ----------------
__device__ __nv_bfloat16 g_W1[K1 * FOURH];   // tc: [(w/GW)*NTILE + g*GW + w%GW][K]; fb: [k][4096]
__device__ __nv_bfloat16 g_W2[K2 * FOURH];
__device__ __nv_bfloat16 g_X[TT * BB * DD];  // [t][b][d]
__device__ __nv_bfloat16 g_h1[2][BB * HH];
__device__ __nv_bfloat16 g_h2[2][BB * HH];
__device__ float g_c1[BB * HH];
__device__ float g_c2[BB * HH];
__device__ float g_partial[BB];
__device__ unsigned g_bar_ctr;

// ---------------- helpers ----------------
__device__ __forceinline__ uint32_t smem_u32(const void* p) {
    return (uint32_t)__cvta_generic_to_shared(p);
}
__device__ __forceinline__ float fast_tanh(float x) {
    float y;
    asm("tanh.approx.f32 %0, %1;" : "=f"(y) : "f"(x));
    return y;
}
__device__ __forceinline__ float fast_sigmoid(float x) {
    return 0.5f * fast_tanh(0.5f * x) + 0.5f;
}
__device__ __forceinline__ float sigmoidf_(float x) { return 1.f / (1.f + __expf(-x)); }

// ---------------- conversion / init kernels ----------------
// tc path: W[k][4096] fp32 -> Wp[(w/gw)*(4*gw) + g*gw + (w%gw)][K] bf16
__global__ void conv_w_t(const float* __restrict__ src, int which, int K, int gw) {
    __shared__ float tile[32][33];
    const int kb = blockIdx.x * 32, wb = blockIdx.y * 32, g = blockIdx.z;
    const int tx = threadIdx.x, ty0 = threadIdx.y;
    const int ntile = 4 * gw;
#pragma unroll
    for (int i = 0; i < 4; i++) {
        int ty = ty0 + i * 8;
        tile[ty][tx] = src[(size_t)(kb + ty) * FOURH + g * HH + wb + tx];
    }
    __syncthreads();
    __nv_bfloat16* dst = (which == 0) ? g_W1 : g_W2;
#pragma unroll
    for (int i = 0; i < 4; i++) {
        int ty = ty0 + i * 8;
        int w = wb + ty;
        int row = (w / gw) * ntile + g * gw + (w % gw);
        dst[(size_t)row * K + kb + tx] = __float2bfloat16(tile[tx][ty]);
    }
}

__global__ void conv_w_kernel(const float* __restrict__ src, int which, int n) {
    for (int i = blockIdx.x * blockDim.x + threadIdx.x; i < n; i += gridDim.x * blockDim.x) {
        __nv_bfloat16 v = __float2bfloat16(src[i]);
        if (which == 0) g_W1[i] = v;
        else            g_W2[i] = v;
    }
}

__global__ void conv_x_kernel(const float* __restrict__ f) {
    int n = BB * TT * DD;
    for (int i = blockIdx.x * blockDim.x + threadIdx.x; i < n; i += gridDim.x * blockDim.x) {
        int b = i / (TT * DD);
        int r = i % (TT * DD);
        int t = r / DD;
        int d = r % DD;
        g_X[(size_t)t * BB * DD + b * DD + d] = __float2bfloat16(f[i]);
    }
}

__global__ void init_state_kernel() {
    int n = BB * HH;
    __nv_bfloat16 z = __float2bfloat16(0.f);
    if (blockIdx.x == 0 && threadIdx.x == 0) g_bar_ctr = 0;
    for (int i = blockIdx.x * blockDim.x + threadIdx.x; i < n; i += gridDim.x * blockDim.x) {
        g_c1[i] = 0.f;
        g_c2[i] = 0.f;
        g_h1[0][i] = z;
        g_h2[0][i] = z;
    }
}

// ============================================================================
// tcgen05 + TMA PTX helpers ('a'-variant targets only)
// ============================================================================
#if HAS_TCGEN05

__device__ __forceinline__ uint32_t elect_one_pred() {
    uint32_t pred;
    asm volatile(
        "{\n\t.reg .pred p;\n\t"
        "elect.sync _|p, 0xFFFFFFFF;\n\t"
        "selp.b32 %0, 1, 0, p;\n\t}"
        : "=r"(pred));
    return pred;
}

#define MBARRIER_INIT(mbar, count) \
    asm volatile("mbarrier.init.shared.b64 [%0], %1;" :: "r"((uint32_t)(mbar)), "r"((uint32_t)(count)) : "memory")

#define MBARRIER_EXPECT_TX(mbar, bytes) \
    asm volatile("mbarrier.arrive.expect_tx.shared.b64 _, [%0], %1;" \
                 :: "r"((uint32_t)(mbar)), "r"((uint32_t)(bytes)) : "memory")

#define MBARRIER_WAIT_PARITY(mbar_addr, phase_parity) do {                          \
    uint32_t _mbar = (uint32_t)(mbar_addr);                                         \
    uint32_t _parity = (uint32_t)(phase_parity);                                    \
    uint32_t _done;                                                                 \
    asm volatile(                                                                   \
        "{\n\t.reg .pred p;\n\t"                                                    \
        "mbarrier.try_wait.parity.acquire.cta.shared::cta.b64 p, [%1], %2;\n\t"     \
        "selp.b32 %0, 1, 0, p;\n\t}"                                                \
        : "=r"(_done) : "r"(_mbar), "r"(_parity) : "memory");                       \
    if (!_done) {                                                                   \
        asm volatile(                                                               \
            "{\n\t.reg .pred P1;\n\t"                                               \
            "WAIT_LOOP_%=:\n\t"                                                     \
            "mbarrier.try_wait.parity.acquire.cta.shared::cta.b64 P1, [%0], %1, 0x989680;\n\t" \
            "@P1 bra.uni WAIT_DONE_%=;\n\t"                                         \
            "bra.uni WAIT_LOOP_%=;\n\t"                                             \
            "WAIT_DONE_%=:\n\t}"                                                    \
            :: "r"(_mbar), "r"(_parity) : "memory");                                \
    }                                                                               \
} while (0)

#define TMA_LOAD_3D_MULTICAST(smem_addr, tensor_map, cx, cy, cz, mbar, cta_mask) \
    asm volatile( \
        "cp.async.bulk.tensor.3d.shared::cluster.global.tile.mbarrier::complete_tx::bytes.multicast::cluster " \
        "[%0], [%1, {%2, %3, %4}], [%5], %6;" \
        :: "r"((uint32_t)(smem_addr)), "l"(tensor_map), \
           "r"((int32_t)(cx)), "r"((int32_t)(cy)), "r"((int32_t)(cz)), \
           "r"((uint32_t)(mbar)), "h"((uint16_t)(cta_mask)) \
        : "memory")

#define CLUSTER_SYNC() do { \
    asm volatile("barrier.cluster.arrive.aligned;" ::: "memory"); \
    asm volatile("barrier.cluster.wait.aligned;" ::: "memory"); \
} while (0)

#define TCGEN05_ALLOC(smem_result_addr, nCols) \
    asm volatile("tcgen05.alloc.cta_group::1.sync.aligned.shared::cta.b32 [%0], %1;" \
                 :: "r"((uint32_t)(smem_result_addr)), "r"((uint32_t)(nCols)) : "memory")
#define TCGEN05_DEALLOC(tmem_addr, nCols) \
    asm volatile("tcgen05.dealloc.cta_group::1.sync.aligned.b32 %0, %1;" \
                 :: "r"(tmem_addr), "r"((uint32_t)(nCols)))
#define TCGEN05_RELINQUISH() \
    asm volatile("tcgen05.relinquish_alloc_permit.cta_group::1.sync.aligned;")
#define TCGEN05_COMMIT(mbar_addr) \
    asm volatile("tcgen05.commit.cta_group::1.mbarrier::arrive::one.shared::cluster.b64 [%0];" \
                 :: "r"((uint32_t)(mbar_addr)) : "memory")
#define TCGEN05_COMMIT_MULTICAST(mbar_addr, cta_mask) \
    asm volatile("tcgen05.commit.cta_group::1.mbarrier::arrive::one.shared::cluster.multicast::cluster.b64 [%0], %1;" \
                 :: "r"((uint32_t)(mbar_addr)), "h"((uint16_t)(cta_mask)) : "memory")
#define TCGEN05_WAIT_LD()  asm volatile("tcgen05.wait::ld.sync.aligned;" ::: "memory")
#define TCGEN05_FENCE_AFTER()  asm volatile("tcgen05.fence::after_thread_sync;" ::: "memory")
#define TCGEN05_FENCE_BEFORE() asm volatile("tcgen05.fence::before_thread_sync;" ::: "memory")

#define TCGEN05_LD_X32(r, tmem_addr) \
    asm volatile( \
        "tcgen05.ld.sync.aligned.32x32b.x32.b32 " \
        "{%0, %1, %2, %3, %4, %5, %6, %7, " \
        " %8, %9, %10, %11, %12, %13, %14, %15, " \
        " %16, %17, %18, %19, %20, %21, %22, %23, " \
        " %24, %25, %26, %27, %28, %29, %30, %31}, [%32];" \
        : "=r"((r)[0]),  "=r"((r)[1]),  "=r"((r)[2]),  "=r"((r)[3]), \
          "=r"((r)[4]),  "=r"((r)[5]),  "=r"((r)[6]),  "=r"((r)[7]), \
          "=r"((r)[8]),  "=r"((r)[9]),  "=r"((r)[10]), "=r"((r)[11]), \
          "=r"((r)[12]), "=r"((r)[13]), "=r"((r)[14]), "=r"((r)[15]), \
          "=r"((r)[16]), "=r"((r)[17]), "=r"((r)[18]), "=r"((r)[19]), \
          "=r"((r)[20]), "=r"((r)[21]), "=r"((r)[22]), "=r"((r)[23]), \
          "=r"((r)[24]), "=r"((r)[25]), "=r"((r)[26]), "=r"((r)[27]), \
          "=r"((r)[28]), "=r"((r)[29]), "=r"((r)[30]), "=r"((r)[31]) \
        : "r"(tmem_addr))

__device__ __forceinline__ uint64_t sdesc_sw128(uint32_t addr) {
    return (2ULL << 61) | (1ULL << 46) | (64ULL << 32) | (1ULL << 16) |
           (uint64_t)((addr >> 4) & 0x3FFF);
}

__device__ __forceinline__ void mma_f16_ss(uint32_t d, uint64_t ad, uint64_t bd,
                                           uint32_t idesc, unsigned en) {
    asm volatile(
        "{\n\t.reg .pred p;\n\t"
        "setp.ne.u32 p, %5, 0;\n\t"
        "tcgen05.mma.cta_group::1.kind::f16 [%0], %1, %2, %3, {%4, %4, %4, %4}, p;\n\t}"
        :: "r"(d), "l"(ad), "l"(bd), "r"(idesc), "r"(0u), "r"(en) : "memory");
}

#endif // HAS_TCGEN05

// ============================================================================
// PERSISTENT templated tcgen05 kernel.
//   CL=8, NTILE=64 : 128 CTAs, cluster 2m x 4nt, A shared x4, B shared x2.
//   CL=4, NTILE=128: 64 CTAs, cluster 2m x 2nt, A shared x2, B shared x2 (proven).
// Warp 0 = MMA issuer, warp 1 = TMA producer, all warps epilogue + grid barrier.
// ============================================================================
template <int CL, int NTILE>
__global__ __launch_bounds__(256, 1)
void lstm_persist(const __grid_constant__ CUtensorMap tmx,
                  const __grid_constant__ CUtensorMap tmh1,
                  const __grid_constant__ CUtensorMap tmh2,
                  const __grid_constant__ CUtensorMap tmw1,
                  const __grid_constant__ CUtensorMap tmw2,
                  const float* __restrict__ b1, const float* __restrict__ b2) {
#if HAS_TCGEN05
    constexpr int STB   = 16384 + NTILE * 128;            // A 16KB + B tile
    constexpr int NSTG  = (NTILE == 64) ? 8 : 6;           // both -> 197632 B total
    constexpr int AROWS = (CL == 8) ? 32 : 64;             // A slice rows per producer
    constexpr int ASLB  = AROWS * 128;                     // A slice bytes
    constexpr int BROWS = NTILE / 2;                       // B slice rows per producer
    constexpr int BSLB  = BROWS * 128;
    constexpr int EMPTY_CNT = (CL == 8) ? 5 : 3;
    constexpr uint32_t IDESC =
        (1u << 4) | (1u << 7) | (1u << 10) | ((NTILE / 8u) << 17) | (8u << 24);

    extern __shared__ __align__(1024) unsigned char sm[];
    const uint32_t smem_base = smem_u32(sm);
    const int tid = threadIdx.x;
    const int wid = tid >> 5;
    const int lane = tid & 31;

    const int r = (int)(blockIdx.x & (CL - 1));
    const int ntg = (int)((blockIdx.x / CL) * (CL / 2) + (r >> 1));
    const int m0 = (r & 1) * 128;
    const int ar = r >> 1;            // A slice index
    const int bm = r & 1;             // B slice index
    uint16_t amask, bmask;
    if constexpr (CL == 8) {
        amask = (uint16_t)(0x55u << (r & 1));
        bmask = (uint16_t)(0x3u << (r & ~1));
    } else {
        amask = (uint16_t)((1u << r) | (1u << (r ^ 2)));
        bmask = (uint16_t)((1u << r) | (1u << (r ^ 1)));
    }
    const uint16_t emask = (uint16_t)(amask | bmask);

    const uint32_t ctrl = smem_base + NSTG * STB;          // tmem ptr (16B)
    const uint32_t mb_full = ctrl + 16;
    const uint32_t mb_empty = mb_full + 8 * NSTG;
    const uint32_t mb_done = mb_empty + 8 * NSTG;

    if (wid == 0) TCGEN05_ALLOC(ctrl, NTILE);
    if (tid == 0) {
#pragma unroll
        for (int s = 0; s < NSTG; s++) {
            MBARRIER_INIT(mb_full + 8 * s, 1);
            MBARRIER_INIT(mb_empty + 8 * s, EMPTY_CNT);
        }
        MBARRIER_INIT(mb_done, 1);
    }
    __syncthreads();
    CLUSTER_SYNC();
    uint32_t tmem_base;
    asm volatile("ld.shared.b32 %0, [%1];" : "=r"(tmem_base) : "r"(ctrl));

    int done_par = 0;
    unsigned gj = 0;
    unsigned bar_n = 0;

    for (int t = 0; t < TT; t++) {
        const int pin = t & 1;
        const int pout = pin ^ 1;
#pragma unroll 1
        for (int layer = 0; layer < 2; layer++) {
            const int nc = (layer == 0) ? (K1 / 64) : (K2 / 64);
            float* cst = (layer == 0) ? g_c1 : g_c2;
            __nv_bfloat16* hout = (layer == 0) ? g_h1[pout] : g_h2[pout];
            const float* bias = (layer == 0) ? b1 : b2;

            if (wid == 1) {
                // ---------------- producer: TMA issuer ----------------
                for (int c = 0; c < nc; ++c) {
                    const unsigned G = gj + (unsigned)c;
                    const int s = (int)(G % NSTG);
                    const unsigned n = G / NSTG;
                    if (n > 0) MBARRIER_WAIT_PARITY(mb_empty + 8 * s, (int)((n - 1) & 1));
                    if (elect_one_pred()) {
                        const uint32_t sbase = smem_base + s * STB;
                        const uint32_t fb = mb_full + 8 * s;
                        MBARRIER_EXPECT_TX(fb, (uint32_t)STB);
                        const int k0 = c * 64;
                        const CUtensorMap* tA;
                        int cxA, czA;
                        if (layer == 0) {
                            if (k0 < DD) { tA = &tmx;  cxA = k0;       czA = t; }
                            else         { tA = &tmh1; cxA = k0 - DD;  czA = pin; }
                        } else {
                            if (k0 < HH) { tA = &tmh1; cxA = k0;       czA = pout; }
                            else         { tA = &tmh2; cxA = k0 - HH;  czA = pin; }
                        }
                        TMA_LOAD_3D_MULTICAST(sbase + ar * ASLB, tA,
                                              cxA, m0 + ar * AROWS, czA, fb, amask);
                        const CUtensorMap* tB = (layer == 0) ? &tmw1 : &tmw2;
                        TMA_LOAD_3D_MULTICAST(sbase + 16384 + bm * BSLB, tB,
                                              k0, ntg * NTILE + bm * BROWS, 0, fb, bmask);
                    }
                }
            } else if (wid == 0) {
                // ---------------- consumer: MMA issuer ----------------
                for (int c = 0; c < nc; ++c) {
                    const unsigned G = gj + (unsigned)c;
                    const int s = (int)(G % NSTG);
                    const unsigned n = G / NSTG;
                    MBARRIER_WAIT_PARITY(mb_full + 8 * s, (int)(n & 1));
                    if (elect_one_pred()) {
                        const uint64_t ad = sdesc_sw128(smem_base + s * STB);
                        const uint64_t bd = sdesc_sw128(smem_base + s * STB + 16384);
#pragma unroll
                        for (int kk = 0; kk < 4; kk++)
                            mma_f16_ss(tmem_base, ad + kk * 2, bd + kk * 2, IDESC,
                                       (unsigned)((c | kk) != 0));
                        TCGEN05_COMMIT_MULTICAST(mb_empty + 8 * s, emask);
                    }
                }
                if (elect_one_pred()) TCGEN05_COMMIT(mb_done);
            }

            // ---- all warps: wait GEMM completion ----
            MBARRIER_WAIT_PARITY(mb_done, done_par);
            done_par ^= 1;
            TCGEN05_FENCE_AFTER();

            // ---- epilogue: LDTM -> smem -> fused LSTM cell ----
            {
                constexpr int HW = NTILE / 4;          // h-cols per CTA (16 or 32)
                constexpr int ZST = NTILE / 2 + 1;     // zs stride (33.. no: 65 or 133? see below)
                // NTILE=64 -> stride 65; NTILE=128 -> stride 133 (128+5 odd pad)
                constexpr int ZSTRIDE = (NTILE == 64) ? 65 : 133;
                const uint32_t cb = (uint32_t)(wid >> 2) * (NTILE / 2);
                float* zs = (float*)sm;
                const int row = (wid & 3) * 32 + lane;
                if constexpr (NTILE == 128) {
                    uint32_t regs[64];
                    TCGEN05_LD_X32(regs, tmem_base + cb);
                    TCGEN05_LD_X32(regs + 32, tmem_base + cb + 32);
                    TCGEN05_WAIT_LD();
                    TCGEN05_FENCE_BEFORE();
#pragma unroll
                    for (int c2 = 0; c2 < 64; c2++)
                        zs[row * ZSTRIDE + cb + c2] = __uint_as_float(regs[c2]);
                } else {
                    uint32_t regs[32];
                    TCGEN05_LD_X32(regs, tmem_base + cb);
                    TCGEN05_WAIT_LD();
                    TCGEN05_FENCE_BEFORE();
#pragma unroll
                    for (int c2 = 0; c2 < 32; c2++)
                        zs[row * ZSTRIDE + cb + c2] = __uint_as_float(regs[c2]);
                }
                __syncthreads();

                const int hb = ntg * HW;
#pragma unroll
                for (int e = tid; e < 128 * HW; e += 256) {
                    const int rr = e / HW;
                    const int hc = e % HW;
                    float zi = zs[rr * ZSTRIDE + hc]          + bias[hb + hc];
                    float zj = zs[rr * ZSTRIDE + HW + hc]     + bias[HH + hb + hc];
                    float zf = zs[rr * ZSTRIDE + 2 * HW + hc] + bias[2 * HH + hb + hc];
                    float zo = zs[rr * ZSTRIDE + 3 * HW + hc] + bias[3 * HH + hb + hc];
                    const int gi = (m0 + rr) * HH + hb + hc;
                    float cc = cst[gi];
                    float ncell = cc * fast_sigmoid(zf + 1.f) +
                                  fast_sigmoid(zi) * fast_tanh(zj);
                    hout[gi] = __float2bfloat16(fast_tanh(ncell) * fast_sigmoid(zo));
                    cst[gi] = ncell;
                }
                (void)ZST;
            }

            gj += (unsigned)nc;

            // ---- grid barrier ----
            bar_n++;
            __syncthreads();
            if (tid == 0) {
                __threadfence();
                atomicAdd(&g_bar_ctr, 1u);
                const unsigned tgt = bar_n * gridDim.x;
                while (*(volatile unsigned*)&g_bar_ctr < tgt) { }
            }
            __syncthreads();
        }
    }

    CLUSTER_SYNC();
    if (wid == 0) {
        TCGEN05_RELINQUISH();
        TCGEN05_DEALLOC(tmem_base, NTILE);
    }
#endif // HAS_TCGEN05
}

// ============================================================================
// Fallback: mma.sync (HMMA) fused step kernel (round-1 proven path).
// ============================================================================
#define AS_STRIDE 40
#define BS_STRIDE 136
#define ZS_STRIDE 132

__global__ __launch_bounds__(256, 1)
void lstm_step_fb(int layer, int t, int pin, const float* __restrict__ bias) {
    __shared__ __align__(16) unsigned char smem_raw[64 * ZS_STRIDE * 4];
    __nv_bfloat16* As = (__nv_bfloat16*)smem_raw;
    __nv_bfloat16* Bs = (__nv_bfloat16*)(smem_raw + 10240);
    float* zs = (float*)smem_raw;

    int K, boundk, lda0;
    const __nv_bfloat16 *A0, *A1, *Wm;
    float* cst;
    __nv_bfloat16* hout;
    const int pout = pin ^ 1;

    if (layer == 0) {
        K = K1; boundk = DD; lda0 = DD;
        A0 = g_X + (size_t)t * BB * DD;
        A1 = g_h1[pin];
        Wm = g_W1; cst = g_c1; hout = g_h1[pout];
    } else {
        K = K2; boundk = HH; lda0 = HH;
        A0 = g_h1[pout];
        A1 = g_h2[pin];
        Wm = g_W2; cst = g_c2; hout = g_h2[pout];
    }

    const int n0 = blockIdx.x * 32;
    const int m0 = blockIdx.y * 64;
    const int tid = threadIdx.x;
    const int lane = tid & 31;
    const int wid = tid >> 5;
    const int wm = wid & 3;
    const int wn = wid >> 2;
    const int rowA = tid >> 2;
    const int quadA = tid & 3;

    float acc[8][4];
#pragma unroll
    for (int j = 0; j < 8; j++)
#pragma unroll
        for (int q = 0; q < 4; q++) acc[j][q] = 0.f;

    auto load_stage = [&](int kt, int s) {
        const int k0 = kt * 32;
        const __nv_bfloat16* gpA;
        if (k0 < boundk) gpA = A0 + (size_t)(m0 + rowA) * lda0 + k0 + quadA * 8;
        else             gpA = A1 + (size_t)(m0 + rowA) * HH + (k0 - boundk) + quadA * 8;
        uint32_t dstA = smem_u32(As + s * 64 * AS_STRIDE + rowA * AS_STRIDE + quadA * 8);
        asm volatile("cp.async.cg.shared.global [%0], [%1], 16;\n" :: "r"(dstA), "l"(gpA));
#pragma unroll
        for (int i = 0; i < 2; i++) {
            int c = tid + i * 256;
            int kk = c >> 4;
            int ncv = (c & 15) * 8;
            int g = ncv >> 5;
            int col = g * HH + n0 + (ncv & 31);
            const __nv_bfloat16* gpB = Wm + (size_t)(k0 + kk) * FOURH + col;
            uint32_t dstB = smem_u32(Bs + s * 32 * BS_STRIDE + kk * BS_STRIDE + ncv);
            asm volatile("cp.async.cg.shared.global [%0], [%1], 16;\n" :: "r"(dstB), "l"(gpB));
        }
    };

    load_stage(0, 0);
    asm volatile("cp.async.commit_group;\n" ::: "memory");

    const int nK = K >> 5;
    for (int kt = 0; kt < nK; ++kt) {
        const int s = kt & 1;
        if (kt + 1 < nK) load_stage(kt + 1, s ^ 1);
        asm volatile("cp.async.commit_group;\n" ::: "memory");
        asm volatile("cp.async.wait_group 1;\n" ::: "memory");
        __syncthreads();

#pragma unroll
        for (int ks = 0; ks < 2; ++ks) {
            uint32_t a0, a1, a2, a3;
            {
                int row = wm * 16 + (lane & 15);
                int colb = ks * 16 + (lane >> 4) * 8;
                uint32_t addr = smem_u32(As + s * 64 * AS_STRIDE + row * AS_STRIDE + colb);
                asm volatile("ldmatrix.sync.aligned.m8n8.x4.shared.b16 {%0,%1,%2,%3}, [%4];\n"
                             : "=r"(a0), "=r"(a1), "=r"(a2), "=r"(a3) : "r"(addr));
            }
#pragma unroll
            for (int j2 = 0; j2 < 4; j2++) {
                uint32_t b0, b1, b2, b3;
                int krow = ks * 16 + (lane & 7) + ((lane >> 3) & 1) * 8;
                int ncol = wn * 64 + j2 * 16 + (lane >> 4) * 8;
                uint32_t addr = smem_u32(Bs + s * 32 * BS_STRIDE + krow * BS_STRIDE + ncol);
                asm volatile("ldmatrix.sync.aligned.m8n8.x4.trans.shared.b16 {%0,%1,%2,%3}, [%4];\n"
                             : "=r"(b0), "=r"(b1), "=r"(b2), "=r"(b3) : "r"(addr));
                asm volatile("mma.sync.aligned.m16n8k16.row.col.f32.bf16.bf16.f32 "
                             "{%0,%1,%2,%3}, {%4,%5,%6,%7}, {%8,%9}, {%0,%1,%2,%3};\n"
                             : "+f"(acc[2 * j2][0]), "+f"(acc[2 * j2][1]),
                               "+f"(acc[2 * j2][2]), "+f"(acc[2 * j2][3])
                             : "r"(a0), "r"(a1), "r"(a2), "r"(a3), "r"(b0), "r"(b1));
                asm volatile("mma.sync.aligned.m16n8k16.row.col.f32.bf16.bf16.f32 "
                             "{%0,%1,%2,%3}, {%4,%5,%6,%7}, {%8,%9}, {%0,%1,%2,%3};\n"
                             : "+f"(acc[2 * j2 + 1][0]), "+f"(acc[2 * j2 + 1][1]),
                               "+f"(acc[2 * j2 + 1][2]), "+f"(acc[2 * j2 + 1][3])
                             : "r"(a0), "r"(a1), "r"(a2), "r"(a3), "r"(b2), "r"(b3));
            }
        }
        __syncthreads();
    }

#pragma unroll
    for (int j = 0; j < 8; j++) {
        int col = wn * 64 + j * 8 + (lane & 3) * 2;
        int rr = wm * 16 + (lane >> 2);
        zs[rr * ZS_STRIDE + col]           = acc[j][0];
        zs[rr * ZS_STRIDE + col + 1]       = acc[j][1];
        zs[(rr + 8) * ZS_STRIDE + col]     = acc[j][2];
        zs[(rr + 8) * ZS_STRIDE + col + 1] = acc[j][3];
    }
    __syncthreads();

#pragma unroll
    for (int e = tid; e < 64 * 32; e += 256) {
        int rr = e >> 5;
        int hc = e & 31;
        float zi = zs[rr * ZS_STRIDE + hc]        + bias[0 * HH + n0 + hc];
        float zj = zs[rr * ZS_STRIDE + 32 + hc]   + bias[1 * HH + n0 + hc];
        float zf = zs[rr * ZS_STRIDE + 64 + hc]   + bias[2 * HH + n0 + hc];
        float zo = zs[rr * ZS_STRIDE + 96 + hc]   + bias[3 * HH + n0 + hc];
        int gi = (m0 + rr) * HH + n0 + hc;
        float c = cst[gi];
        float ncell = c * sigmoidf_(zf + 1.f) + sigmoidf_(zi) * tanhf(zj);
        float nh = tanhf(ncell) * sigmoidf_(zo);
        cst[gi] = ncell;
        hout[gi] = __float2bfloat16(nh);
    }
}

// ---------------- dense head + loss ----------------
__global__ void head_kernel(const float* __restrict__ Wd, const float* __restrict__ bd,
                            const float* __restrict__ labels) {
    const int b = blockIdx.x;
    const int lane = threadIdx.x & 31;
    const int w = threadIdx.x >> 5;
    const __nv_bfloat16* h = g_h2[0];  // T=336 even -> final h2 in slot 0
    __shared__ float warpsum[8];
    float total = 0.f;
    for (int l = w; l < 24; l += 8) {
        float s = 0.f;
        for (int k = lane; k < HH; k += 32)
            s += __bfloat162float(h[b * HH + k]) * Wd[k * 24 + l];
#pragma unroll
        for (int off = 16; off; off >>= 1) s += __shfl_xor_sync(0xffffffffu, s, off);
        if (lane == 0) {
            float pred = s + bd[l];
            float e = pred - labels[b * 24 + l];
            total += e * e;
        }
    }
    if (lane == 0) warpsum[w] = total;
    __syncthreads();
    if (threadIdx.x == 0) {
        float acc = 0.f;
#pragma unroll
        for (int i = 0; i < 8; i++) acc += warpsum[i];
        g_partial[b] = acc;
    }
}

__global__ void finish_kernel(float* __restrict__ out) {
    __shared__ float sh[256];
    sh[threadIdx.x] = g_partial[threadIdx.x];
    __syncthreads();
    for (int s = 128; s; s >>= 1) {
        if (threadIdx.x < s) sh[threadIdx.x] += sh[threadIdx.x + s];
        __syncthreads();
    }
    if (threadIdx.x == 0) out[0] = sh[0] / (float)(BB * 24);
}

// ---------------- host: tensormap encoding ----------------
typedef CUresult (*encode_fn_t)(
    CUtensorMap*, CUtensorMapDataType, cuuint32_t, void*,
    const cuuint64_t*, const cuuint64_t*, const cuuint32_t*, const cuuint32_t*,
    CUtensorMapInterleave, CUtensorMapSwizzle, CUtensorMapL2promotion,
    CUtensorMapFloatOOBfill);

static bool encode_map(encode_fn_t enc, CUtensorMap* tm, void* base,
                       uint64_t d0, uint64_t d1, uint64_t d2,
                       uint64_t s1_bytes, uint64_t s2_bytes, uint32_t box_rows) {
    cuuint64_t dims[3] = {d0, d1, d2};
    cuuint64_t strides[2] = {s1_bytes, s2_bytes};
    cuuint32_t box[3] = {64, box_rows, 1};
    cuuint32_t es[3] = {1, 1, 1};
    CUresult res = enc(tm, CU_TENSOR_MAP_DATA_TYPE_BFLOAT16, 3, base,
                       dims, strides, box, es,
                       CU_TENSOR_MAP_INTERLEAVE_NONE, CU_TENSOR_MAP_SWIZZLE_128B,
                       CU_TENSOR_MAP_L2_PROMOTION_L2_128B,
                       CU_TENSOR_MAP_FLOAT_OOB_FILL_NONE);
    return res == CUDA_SUCCESS;
}

// ---------------- launch ----------------
extern "C" void kernel_launch(void* const* d_in, const int* in_sizes, int n_in,
                              void* d_out, int out_size) {
    const float* features = (const float*)d_in[0];
    const float* labels   = (const float*)d_in[1];
    const float* W1       = (const float*)d_in[2];
    const float* b1       = (const float*)d_in[3];
    const float* W2       = (const float*)d_in[4];
    const float* b2       = (const float*)d_in[5];
    const float* Wd       = (const float*)d_in[6];
    const float* bd       = (const float*)d_in[7];
    float* out = (float*)d_out;

    constexpr int SMEM_DYN_A = 8 * 24576 + 1024;   // <8,64>
    constexpr int SMEM_DYN_B = 6 * 32768 + 1024;   // <4,128>

    static CUtensorMap tmx, tmh1, tmh2, tmw1, tmw2;
    static int mode = -1;   // 0 = mma.sync fallback, 1 = cfgB <4,128>, 2 = cfgA <8,64>
    if (mode < 0) {
        mode = 0;
        cudaFuncAttributes attr{};
        cudaFuncGetAttributes(&attr, lstm_persist<4, 128>);
        if (attr.numRegs > 40) {
            void* fp = nullptr;
            cudaDriverEntryPointQueryResult qr = cudaDriverEntryPointSuccess;
            cudaGetDriverEntryPointByVersion("cuTensorMapEncodeTiled", &fp, 12000,
                                             cudaEnableDefault, &qr);
            void *px = nullptr, *ph1 = nullptr, *ph2 = nullptr, *pw1 = nullptr, *pw2 = nullptr;
            cudaGetSymbolAddress(&px, g_X);
            cudaGetSymbolAddress(&ph1, g_h1);
            cudaGetSymbolAddress(&ph2, g_h2);
            cudaGetSymbolAddress(&pw1, g_W1);
            cudaGetSymbolAddress(&pw2, g_W2);
            if (fp && px && ph1 && ph2 && pw1 && pw2) {
                // Can cfgA's 16 clusters of 8 be simultaneously resident?
                int use_a = 0;
                if (cudaFuncSetAttribute(lstm_persist<8, 64>,
                        cudaFuncAttributeMaxDynamicSharedMemorySize, SMEM_DYN_A)
                        == cudaSuccess) {
                    cudaLaunchConfig_t qcfg = {};
                    qcfg.gridDim = dim3(128, 1, 1);
                    qcfg.blockDim = dim3(256, 1, 1);
                    qcfg.dynamicSmemBytes = SMEM_DYN_A;
                    cudaLaunchAttribute qat[1];
                    qat[0].id = cudaLaunchAttributeClusterDimension;
                    qat[0].val.clusterDim = {8, 1, 1};
                    qcfg.attrs = qat;
                    qcfg.numAttrs = 1;
                    int nclust = 0;
                    if (cudaOccupancyMaxActiveClusters(&nclust, lstm_persist<8, 64>, &qcfg)
                            == cudaSuccess && nclust >= 16)
                        use_a = 1;
                }
                const uint32_t brows = use_a ? 32u : 64u;
                encode_fn_t enc = (encode_fn_t)fp;
                bool ok = true;
                ok &= encode_map(enc, &tmx,  px,  DD, BB, TT, (uint64_t)DD * 2, (uint64_t)BB * DD * 2, brows);
                ok &= encode_map(enc, &tmh1, ph1, HH, BB, 2,  (uint64_t)HH * 2, (uint64_t)BB * HH * 2, brows);
                ok &= encode_map(enc, &tmh2, ph2, HH, BB, 2,  (uint64_t)HH * 2, (uint64_t)BB * HH * 2, brows);
                ok &= encode_map(enc, &tmw1, pw1, K1, FOURH, 1, (uint64_t)K1 * 2, (uint64_t)K1 * FOURH * 2, brows);
                ok &= encode_map(enc, &tmw2, pw2, K2, FOURH, 1, (uint64_t)K2 * 2, (uint64_t)K2 * FOURH * 2, brows);
                if (ok) {
                    mode = use_a ? 2 : 1;
                    if (mode == 1)
                        cudaFuncSetAttribute(lstm_persist<4, 128>,
                                             cudaFuncAttributeMaxDynamicSharedMemorySize, SMEM_DYN_B);
                }
            }
        }
    }

    if (mode == 2)      conv_w_t<<<dim3(K1 / 32, 32, 4), dim3(32, 8)>>>(W1, 0, K1, 16);
    else if (mode == 1) conv_w_t<<<dim3(K1 / 32, 32, 4), dim3(32, 8)>>>(W1, 0, K1, 32);
    else                conv_w_kernel<<<592, 256>>>(W1, 0, K1 * FOURH);
    if (mode == 2)      conv_w_t<<<dim3(K2 / 32, 32, 4), dim3(32, 8)>>>(W2, 1, K2, 16);
    else if (mode == 1) conv_w_t<<<dim3(K2 / 32, 32, 4), dim3(32, 8)>>>(W2, 1, K2, 32);
    else                conv_w_kernel<<<592, 256>>>(W2, 1, K2 * FOURH);
    conv_x_kernel<<<592, 256>>>(features);
    init_state_kernel<<<512, 256>>>();

    if (mode == 2) {
        cudaLaunchConfig_t cfg = {};
        cfg.gridDim = dim3(128, 1, 1);
        cfg.blockDim = dim3(256, 1, 1);
        cfg.dynamicSmemBytes = SMEM_DYN_A;
        cudaLaunchAttribute at[1];
        at[0].id = cudaLaunchAttributeClusterDimension;
        at[0].val.clusterDim = {8, 1, 1};
        cfg.attrs = at;
        cfg.numAttrs = 1;
        cudaLaunchKernelEx(&cfg, lstm_persist<8, 64>, tmx, tmh1, tmh2, tmw1, tmw2, b1, b2);
    } else if (mode == 1) {
        cudaLaunchConfig_t cfg = {};
        cfg.gridDim = dim3(64, 1, 1);
        cfg.blockDim = dim3(256, 1, 1);
        cfg.dynamicSmemBytes = SMEM_DYN_B;
        cudaLaunchAttribute at[1];
        at[0].id = cudaLaunchAttributeClusterDimension;
        at[0].val.clusterDim = {4, 1, 1};
        cfg.attrs = at;
        cfg.numAttrs = 1;
        cudaLaunchKernelEx(&cfg, lstm_persist<4, 128>, tmx, tmh1, tmh2, tmw1, tmw2, b1, b2);
    } else {
        dim3 grid(32, 4);
        for (int t = 0; t < TT; t++) {
            int p = t & 1;
            lstm_step_fb<<<grid, 256>>>(0, t, p, b1);
            lstm_step_fb<<<grid, 256>>>(1, t, p, b2);
        }
    }

    head_kernel<<<BB, 256>>>(Wd, bd, labels);
    finish_kernel<<<1, 256>>>(out);
}